// round 2
// baseline (speedup 1.0000x reference)
#include <cuda_runtime.h>
#include <math.h>

#define W 384
#define H 384
#define HW (W*H)
#define NIMG 24

// ---------------- scratch (no allocations allowed) ----------------
__device__ float g_dirf[28*225];          // 4+8+16 oriented 15x15 filters
__device__ float g_lpf[25];               // 5x5 gaussian
__device__ float g_bp[3][NIMG*HW];        // bandpasses
__device__ float g_lp[2][NIMG*HW];        // intermediate lowpasses

// ---------------- filter init (deterministic, double to match numpy) ----------------
__global__ void init_filters_kernel() {
    int f = threadIdx.x;
    if (f < 28) {
        int s, d, nd;
        if (f < 4)       { s = 0; d = f;      nd = 4;  }
        else if (f < 12) { s = 1; d = f - 4;  nd = 8;  }
        else             { s = 2; d = f - 12; nd = 16; }
        double scale = (double)(s + 1);
        double sx = 2.0 * scale, sy = 0.5 * scale;
        double ang = 3.14159265358979323846 * (double)d / (double)nd;
        double ca = cos(ang), sa = sin(ang);
        double k[225];
        double sum = 0.0;
        for (int i = 0; i < 15; i++) {
            for (int j = 0; j < 15; j++) {
                double X = (double)(j - 7);
                double Y = (double)(i - 7);
                double Xr = X * ca - Y * sa;
                double Yr = X * sa + Y * ca;
                double v = exp(-0.5 * (Xr*Xr/(sx*sx) + Yr*Yr/(sy*sy))) * Xr / (sx*sx);
                k[i*15 + j] = v;
                sum += v;
            }
        }
        double mean = sum / 225.0;
        double nr = 0.0;
        for (int i = 0; i < 225; i++) { k[i] -= mean; nr += k[i]*k[i]; }
        nr = sqrt(nr);
        double inv = (nr > 1e-6) ? 1.0 / nr : 1.0;
        for (int i = 0; i < 225; i++)
            g_dirf[f*225 + i] = (float)(k[i] * inv);
    } else if (f == 28) {
        double g[5]; double s1 = 0.0;
        for (int i = 0; i < 5; i++) { double a = (double)(i - 2); g[i] = exp(-0.5*a*a); s1 += g[i]; }
        double k1[5];
        for (int i = 0; i < 5; i++) k1[i] = g[i] / s1;
        double k2[25]; double s2 = 0.0;
        for (int i = 0; i < 5; i++)
            for (int j = 0; j < 5; j++) { k2[i*5+j] = k1[i]*k1[j]; s2 += k2[i*5+j]; }
        for (int i = 0; i < 25; i++) g_lpf[i] = (float)(k2[i] / s2);
    }
}

__device__ __forceinline__ int reflect_idx(int i, int n) {
    if (i < 0) return -i;
    if (i >= n) return 2*n - 2 - i;
    return i;
}

// ---------------- Laplacian pyramid stage: lp = G*cur (reflect), bp = cur - lp ----------------
__global__ void lp_stage_kernel(const float* __restrict__ xin,
                                float* __restrict__ dout, int stage) {
    __shared__ float sf[25];
    if (threadIdx.x < 25) sf[threadIdx.x] = g_lpf[threadIdx.x];
    __syncthreads();
    int idx = blockIdx.x * blockDim.x + threadIdx.x;
    if (idx >= NIMG*HW) return;
    int img = idx / HW;
    int p   = idx - img*HW;
    int y = p / W, x = p - y*W;
    const float* cur = (stage == 0) ? xin : g_lp[stage - 1];
    const float* base = cur + (size_t)img*HW;
    float acc = 0.f;
    #pragma unroll
    for (int i = 0; i < 5; i++) {
        int yy = reflect_idx(y + i - 2, H);
        #pragma unroll
        for (int j = 0; j < 5; j++) {
            int xx = reflect_idx(x + j - 2, W);
            acc += sf[i*5 + j] * __ldg(base + yy*W + xx);
        }
    }
    g_bp[stage][idx] = base[p] - acc;
    if (stage < 2) {
        g_lp[stage][idx] = acc;
    } else {
        int b = img / 3, c = img % 3;
        dout[(size_t)(b*87 + c*29 + 28)*HW + p] = acc;   // final lowpass channel
    }
}

// ---------------- directional 15x15 conv, all dirs of one scale per block ----------------
#define TILE_W 64
#define TILE_H 32
#define SROWS (TILE_H + 14)      // 46
#define SCOLS (TILE_W + 14)      // 78
#define SSTR  80                 // padded row stride (multiple of 4 for float4)

__global__ __launch_bounds__(256) void dir_conv_kernel(float* __restrict__ dout) {
    __shared__ float s_in[SROWS * SSTR];     // 46*80 = 3680 floats
    __shared__ float s_f[16 * 225];          // up to 3600 floats

    int z   = blockIdx.z;
    int img = z / 3;
    int s   = z - img*3;
    int nd    = (s == 0) ? 4 : (s == 1) ? 8 : 16;
    int fbase = (s == 0) ? 0 : (s == 1) ? 4 : 12;

    int x0 = blockIdx.x * TILE_W;
    int y0 = blockIdx.y * TILE_H;
    const float* bp = g_bp[s] + (size_t)img*HW;
    int tid = threadIdx.x;

    // load this scale's filters
    for (int i = tid; i < nd*225; i += 256)
        s_f[i] = g_dirf[fbase*225 + i];
    // load input tile with 7-halo (reflect at image borders)
    for (int i = tid; i < SROWS*SCOLS; i += 256) {
        int r = i / SCOLS, c = i - r*SCOLS;
        int gy = reflect_idx(y0 + r - 7, H);
        int gx = reflect_idx(x0 + c - 7, W);
        s_in[r*SSTR + c] = __ldg(bp + gy*W + gx);
    }
    __syncthreads();

    int tx = tid & 7;        // 8 x-groups, each 8 px wide
    int ty = tid >> 3;       // 32 rows
    int b  = img / 3, cc = img % 3;
    const float* srow0 = &s_in[ty*SSTR + tx*8];
    size_t outpix = (size_t)(y0 + ty)*W + x0 + tx*8;

    #pragma unroll 1
    for (int d = 0; d < nd; d++) {
        float acc[8];
        #pragma unroll
        for (int t = 0; t < 8; t++) acc[t] = 0.f;
        const float* fd = &s_f[d*225];
        #pragma unroll 1
        for (int ky = 0; ky < 15; ky++) {
            const float4* rp = (const float4*)(srow0 + ky*SSTR);
            float r[24];
            #pragma unroll
            for (int q = 0; q < 6; q++) {
                float4 v = rp[q];
                r[4*q] = v.x; r[4*q+1] = v.y; r[4*q+2] = v.z; r[4*q+3] = v.w;
            }
            const float* fr = fd + ky*15;
            #pragma unroll
            for (int kx = 0; kx < 15; kx++) {
                float w = fr[kx];
                #pragma unroll
                for (int t = 0; t < 8; t++)
                    acc[t] = fmaf(r[kx + t], w, acc[t]);
            }
        }
        float* op = dout + (size_t)(b*87 + cc*29 + fbase + d)*HW + outpix;
        float4 o0 = make_float4(acc[0], acc[1], acc[2], acc[3]);
        float4 o1 = make_float4(acc[4], acc[5], acc[6], acc[7]);
        ((float4*)op)[0] = o0;
        ((float4*)op)[1] = o1;
    }
}

// ---------------- launch ----------------
extern "C" void kernel_launch(void* const* d_in, const int* in_sizes, int n_in,
                              void* d_out, int out_size) {
    const float* x = (const float*)d_in[0];
    float* out = (float*)d_out;

    init_filters_kernel<<<1, 32>>>();

    int nthreads = NIMG*HW;
    int blocks = (nthreads + 255) / 256;
    lp_stage_kernel<<<blocks, 256>>>(x, out, 0);
    lp_stage_kernel<<<blocks, 256>>>(x, out, 1);
    lp_stage_kernel<<<blocks, 256>>>(x, out, 2);

    dim3 grid(W / TILE_W, H / TILE_H, NIMG * 3);   // 6 x 12 x 72
    dir_conv_kernel<<<grid, 256>>>(out);
}

// round 3
// speedup vs baseline: 1.3825x; 1.3825x over previous
#include <cuda_runtime.h>
#include <math.h>

#define W 384
#define H 384
#define HW (W*H)
#define NIMG 24

// ---------------- scratch (no allocations allowed) ----------------
__device__ float g_dirf[28*225];          // 4+8+16 oriented 15x15 filters
__device__ float g_lpf[25];               // 5x5 gaussian
__device__ float g_bp[3][NIMG*HW];        // bandpasses
__device__ float g_lp[2][NIMG*HW];        // intermediate lowpasses

// ---------------- f32x2 packed-math helpers ----------------
__device__ __forceinline__ unsigned long long pk2(float v) {
    unsigned long long r;
    asm("mov.b64 %0, {%1, %1};" : "=l"(r) : "f"(v));
    return r;
}
__device__ __forceinline__ unsigned long long fma2(unsigned long long a,
                                                   unsigned long long b,
                                                   unsigned long long c) {
    unsigned long long r;
    asm("fma.rn.f32x2 %0, %1, %2, %3;" : "=l"(r) : "l"(a), "l"(b), "l"(c));
    return r;
}
__device__ __forceinline__ float2 up2(unsigned long long v) {
    float2 f;
    asm("mov.b64 {%0, %1}, %2;" : "=f"(f.x), "=f"(f.y) : "l"(v));
    return f;
}

// ---------------- filter init (deterministic, double to match numpy) ----------------
__global__ void init_filters_kernel() {
    int f = threadIdx.x;
    if (f < 28) {
        int s, d, nd;
        if (f < 4)       { s = 0; d = f;      nd = 4;  }
        else if (f < 12) { s = 1; d = f - 4;  nd = 8;  }
        else             { s = 2; d = f - 12; nd = 16; }
        double scale = (double)(s + 1);
        double sx = 2.0 * scale, sy = 0.5 * scale;
        double ang = 3.14159265358979323846 * (double)d / (double)nd;
        double ca = cos(ang), sa = sin(ang);
        double k[225];
        double sum = 0.0;
        for (int i = 0; i < 15; i++) {
            for (int j = 0; j < 15; j++) {
                double X = (double)(j - 7);
                double Y = (double)(i - 7);
                double Xr = X * ca - Y * sa;
                double Yr = X * sa + Y * ca;
                double v = exp(-0.5 * (Xr*Xr/(sx*sx) + Yr*Yr/(sy*sy))) * Xr / (sx*sx);
                k[i*15 + j] = v;
                sum += v;
            }
        }
        double mean = sum / 225.0;
        double nr = 0.0;
        for (int i = 0; i < 225; i++) { k[i] -= mean; nr += k[i]*k[i]; }
        nr = sqrt(nr);
        double inv = (nr > 1e-6) ? 1.0 / nr : 1.0;
        for (int i = 0; i < 225; i++)
            g_dirf[f*225 + i] = (float)(k[i] * inv);
    } else if (f == 28) {
        double g[5]; double s1 = 0.0;
        for (int i = 0; i < 5; i++) { double a = (double)(i - 2); g[i] = exp(-0.5*a*a); s1 += g[i]; }
        double k1[5];
        for (int i = 0; i < 5; i++) k1[i] = g[i] / s1;
        double k2[25]; double s2 = 0.0;
        for (int i = 0; i < 5; i++)
            for (int j = 0; j < 5; j++) { k2[i*5+j] = k1[i]*k1[j]; s2 += k2[i*5+j]; }
        for (int i = 0; i < 25; i++) g_lpf[i] = (float)(k2[i] / s2);
    }
}

__device__ __forceinline__ int reflect_idx(int i, int n) {
    if (i < 0) return -i;
    if (i >= n) return 2*n - 2 - i;
    return i;
}

// ---------------- Laplacian pyramid stage: lp = G*cur (reflect), bp = cur - lp ----
// 4 px per thread, float4 row loads on the interior fast path.
#define XG4 (W/4)   // 96 groups per row
__global__ __launch_bounds__(256) void lp_stage_kernel(const float* __restrict__ xin,
                                                       float* __restrict__ dout, int stage) {
    __shared__ float sf[25];
    if (threadIdx.x < 25) sf[threadIdx.x] = g_lpf[threadIdx.x];
    __syncthreads();
    int gid = blockIdx.x * blockDim.x + threadIdx.x;
    int total = NIMG * H * XG4;
    if (gid >= total) return;
    int img = gid / (H * XG4);
    int rem = gid - img * (H * XG4);
    int y  = rem / XG4;
    int x4 = (rem - y * XG4) * 4;

    const float* cur  = (stage == 0) ? xin : g_lp[stage - 1];
    const float* base = cur + (size_t)img * HW;

    float acc[4] = {0.f, 0.f, 0.f, 0.f};
    if (y >= 2 && y <= H - 3 && x4 >= 4 && x4 <= W - 8) {
        const float* p = base + (size_t)y * W + x4;
        #pragma unroll
        for (int i = 0; i < 5; i++) {
            const float4* rp = (const float4*)(p + (i - 2) * W - 4);
            float r[12];
            #pragma unroll
            for (int q = 0; q < 3; q++) {
                float4 v = __ldg(&rp[q]);
                r[4*q] = v.x; r[4*q+1] = v.y; r[4*q+2] = v.z; r[4*q+3] = v.w;
            }
            #pragma unroll
            for (int j = 0; j < 5; j++) {
                float w = sf[i*5 + j];
                #pragma unroll
                for (int t = 0; t < 4; t++)
                    acc[t] = fmaf(r[2 + j + t], w, acc[t]);
            }
        }
    } else {
        #pragma unroll
        for (int i = 0; i < 5; i++) {
            int yy = reflect_idx(y + i - 2, H);
            #pragma unroll
            for (int j = 0; j < 5; j++) {
                float w = sf[i*5 + j];
                #pragma unroll
                for (int t = 0; t < 4; t++) {
                    int xx = reflect_idx(x4 + t + j - 2, W);
                    acc[t] = fmaf(__ldg(base + yy*W + xx), w, acc[t]);
                }
            }
        }
    }

    size_t p0 = (size_t)img * HW + (size_t)y * W + x4;
    float4 cv = *(const float4*)(base + (size_t)y * W + x4);
    float4 bpv = make_float4(cv.x - acc[0], cv.y - acc[1], cv.z - acc[2], cv.w - acc[3]);
    *(float4*)&g_bp[stage][p0] = bpv;
    if (stage < 2) {
        *(float4*)&g_lp[stage][p0] = make_float4(acc[0], acc[1], acc[2], acc[3]);
    } else {
        int b = img / 3, c = img % 3;
        float* op = dout + (size_t)(b*87 + c*29 + 28) * HW + (size_t)y * W + x4;
        *(float4*)op = make_float4(acc[0], acc[1], acc[2], acc[3]);
    }
}

// ---------------- directional 15x15 conv: 2 images packed per f32x2 lane -----
#define TILE_W 64
#define TILE_H 32
#define SROWS  46            // TILE_H + 14
#define SCOL2  78            // TILE_W + 14 (float2 units); 624B row stride
                             // -> consecutive-row lanes hit distinct bank groups

__global__ __launch_bounds__(256) void dir_conv_kernel(float* __restrict__ dout) {
    __shared__ float2 s_in[SROWS * SCOL2];   // 28704 B, lo=imgA hi=imgB
    __shared__ float  s_f[16 * 225];         // 14400 B

    int z  = blockIdx.z;
    int pr = z / 3;              // image pair 0..11
    int s  = z - pr * 3;
    int imgA = pr * 2;
    int nd    = 4 << s;          // 4, 8, 16
    int fbase = (s == 0) ? 0 : (s == 1) ? 4 : 12;

    int x0 = blockIdx.x * TILE_W;
    int y0 = blockIdx.y * TILE_H;
    const float* bpA = g_bp[s] + (size_t)imgA * HW;
    const float* bpB = bpA + HW;
    int tid = threadIdx.x;

    for (int i = tid; i < nd * 225; i += 256)
        s_f[i] = g_dirf[fbase*225 + i];
    for (int i = tid; i < SROWS * SCOL2; i += 256) {
        int r = i / SCOL2, c = i - r * SCOL2;
        int gy = reflect_idx(y0 + r - 7, H);
        int gx = reflect_idx(x0 + c - 7, W);
        int o = gy * W + gx;
        s_in[i] = make_float2(__ldg(bpA + o), __ldg(bpB + o));
    }
    __syncthreads();

    // lane mapping: consecutive 8 lanes = consecutive rows (conflict-free LDS.128)
    int sub = tid & 7;              // row within group of 8
    int xg  = (tid >> 3) & 7;       // 8 x-groups of 8 px
    int rg  = tid >> 6;             // 4 row groups
    int ty  = sub + rg * 8;         // 0..31

    const double* srow0 = (const double*)&s_in[ty * SCOL2 + xg * 8];

    int imgB = imgA + 1;
    size_t outoff = (size_t)(y0 + ty) * W + x0 + xg * 8;
    float* outA = dout + ((size_t)((imgA/3)*87 + (imgA%3)*29 + fbase)) * HW + outoff;
    float* outB = dout + ((size_t)((imgB/3)*87 + (imgB%3)*29 + fbase)) * HW + outoff;

    #pragma unroll 1
    for (int d = 0; d < nd; d++) {
        unsigned long long acc[8];
        #pragma unroll
        for (int t = 0; t < 8; t++) acc[t] = 0ull;
        const float* fd = &s_f[d * 225];
        #pragma unroll 1
        for (int ky = 0; ky < 15; ky++) {
            const double2* rp = (const double2*)(srow0 + ky * SCOL2);
            double r2[22];
            #pragma unroll
            for (int q = 0; q < 11; q++) {
                double2 v = rp[q];
                r2[2*q] = v.x; r2[2*q+1] = v.y;
            }
            const float* fr = fd + ky * 15;
            #pragma unroll
            for (int kx = 0; kx < 15; kx++) {
                unsigned long long w2 = pk2(fr[kx]);
                #pragma unroll
                for (int t = 0; t < 8; t++)
                    acc[t] = fma2(__double_as_longlong(r2[kx + t]), w2, acc[t]);
            }
        }
        float2 u0 = up2(acc[0]), u1 = up2(acc[1]), u2 = up2(acc[2]), u3 = up2(acc[3]);
        float2 u4 = up2(acc[4]), u5 = up2(acc[5]), u6 = up2(acc[6]), u7 = up2(acc[7]);
        float* oa = outA + (size_t)d * HW;
        float* ob = outB + (size_t)d * HW;
        ((float4*)oa)[0] = make_float4(u0.x, u1.x, u2.x, u3.x);
        ((float4*)oa)[1] = make_float4(u4.x, u5.x, u6.x, u7.x);
        ((float4*)ob)[0] = make_float4(u0.y, u1.y, u2.y, u3.y);
        ((float4*)ob)[1] = make_float4(u4.y, u5.y, u6.y, u7.y);
    }
}

// ---------------- launch ----------------
extern "C" void kernel_launch(void* const* d_in, const int* in_sizes, int n_in,
                              void* d_out, int out_size) {
    const float* x = (const float*)d_in[0];
    float* out = (float*)d_out;

    init_filters_kernel<<<1, 32>>>();

    int groups = NIMG * H * XG4;
    int blocks = (groups + 255) / 256;
    lp_stage_kernel<<<blocks, 256>>>(x, out, 0);
    lp_stage_kernel<<<blocks, 256>>>(x, out, 1);
    lp_stage_kernel<<<blocks, 256>>>(x, out, 2);

    dim3 grid(W / TILE_W, H / TILE_H, (NIMG/2) * 3);   // 6 x 12 x 36
    dir_conv_kernel<<<grid, 256>>>(out);
}

// round 5
// speedup vs baseline: 1.6294x; 1.1786x over previous
#include <cuda_runtime.h>
#include <math.h>

#define W 384
#define H 384
#define HW (W*H)
#define NIMG 24

// ---------------- scratch (no allocations allowed) ----------------
__device__ float g_bp[3][NIMG*HW];        // bandpasses
__device__ float g_lp[2][NIMG*HW];        // intermediate lowpasses

// =====================================================================
// Compile-time double-precision math (matches numpy float64 to ~1e-15)
// =====================================================================
constexpr double PI_ = 3.14159265358979323846264338327950288;

constexpr double cexp(double x) {
    const double LN2 = 0.69314718055994530941723212145817657;
    int n = (int)(x / LN2 + (x >= 0 ? 0.5 : -0.5));
    double r = x - (double)n * LN2;
    double t = 1.0, term = 1.0;
    for (int i = 1; i <= 22; i++) { term *= r / (double)i; t += term; }
    double s = 1.0;
    if (n >= 0) for (int i = 0; i < n; i++)  s *= 2.0;
    else        for (int i = 0; i < -n; i++) s *= 0.5;
    return t * s;
}
constexpr double ccos(double x) {   // x in [0, pi)
    double t = x; bool neg = false;
    if (t > PI_ * 0.5) { t = PI_ - t; neg = true; }
    double t2 = t*t, term = 1.0, s = 1.0;
    for (int i = 1; i <= 16; i++) { term *= -t2 / (double)((2*i-1)*(2*i)); s += term; }
    return neg ? -s : s;
}
constexpr double csin(double x) {   // x in [0, pi)
    double t = x;
    if (t > PI_ * 0.5) t = PI_ - t;     // sin(pi - t) = sin(t)
    double t2 = t*t, term = t, s = t;
    for (int i = 1; i <= 16; i++) { term *= -t2 / (double)((2*i)*(2*i+1)); s += term; }
    return s;
}
constexpr double csqrt(double x) {
    if (x <= 0.0) return 0.0;
    double y = (x > 1.0) ? x : 1.0;
    for (int i = 0; i < 80; i++) y = 0.5 * (y + x / y);
    return y;
}

// ---------------- oriented 15x15 filters, computed at compile time ----------------
struct F225 { float w[225]; };

constexpr F225 make_filt(int s, int d, int nd) {
    double scale = (double)(s + 1);
    double sx = 2.0 * scale, sy = 0.5 * scale;
    double ang = PI_ * (double)d / (double)nd;
    double ca = ccos(ang), sa = csin(ang);
    double k[225] = {};
    double sum = 0.0;
    for (int i = 0; i < 15; i++) {
        for (int j = 0; j < 15; j++) {
            double X = (double)(j - 7), Y = (double)(i - 7);
            double Xr = X * ca - Y * sa;
            double Yr = X * sa + Y * ca;
            double v = cexp(-0.5 * (Xr*Xr/(sx*sx) + Yr*Yr/(sy*sy))) * Xr / (sx*sx);
            k[i*15 + j] = v;
            sum += v;
        }
    }
    double mean = sum / 225.0;
    double nr = 0.0;
    for (int i = 0; i < 225; i++) { k[i] -= mean; nr += k[i]*k[i]; }
    nr = csqrt(nr);
    double inv = (nr > 1e-6) ? 1.0 / nr : 1.0;
    F225 f{};
    for (int i = 0; i < 225; i++) f.w[i] = (float)(k[i] * inv);
    return f;
}

template<int S, int D, int ND>
struct Filt { static constexpr F225 f = make_filt(S, D, ND); };
template<int S, int D, int ND> constexpr F225 Filt<S, D, ND>::f;

// ---------------- 5x5 gaussian lowpass at compile time ----------------
struct F25 { float w[25]; };
constexpr F25 make_lp() {
    double g[5] = {}; double s1 = 0.0;
    for (int i = 0; i < 5; i++) { double a = (double)(i - 2); g[i] = cexp(-0.5*a*a); s1 += g[i]; }
    double k1[5] = {};
    for (int i = 0; i < 5; i++) k1[i] = g[i] / s1;
    double k2[25] = {}; double s2 = 0.0;
    for (int i = 0; i < 5; i++)
        for (int j = 0; j < 5; j++) { k2[i*5+j] = k1[i]*k1[j]; s2 += k2[i*5+j]; }
    F25 f{};
    for (int i = 0; i < 25; i++) f.w[i] = (float)(k2[i] / s2);
    return f;
}
struct LPF { static constexpr F25 f = make_lp(); };
constexpr F25 LPF::f;

__device__ __forceinline__ int reflect_idx(int i, int n) {
    if (i < 0) return -i;
    if (i >= n) return 2*n - 2 - i;
    return i;
}

// =====================================================================
// Laplacian pyramid stage (immediate-weight 5x5), 4 px/thread
// Convention (both paths): r[u] = pixel at x4 + u - 4
// =====================================================================
template<int I, int J>
struct LpTap {
    static __device__ __forceinline__ void run(const float (&r)[12], float (&acc)[4]) {
        constexpr float w = LPF::f.w[I*5 + J];
        acc[0] = fmaf(r[2 + J + 0], w, acc[0]);
        acc[1] = fmaf(r[2 + J + 1], w, acc[1]);
        acc[2] = fmaf(r[2 + J + 2], w, acc[2]);
        acc[3] = fmaf(r[2 + J + 3], w, acc[3]);
        LpTap<I, J+1>::run(r, acc);
    }
};
template<int I> struct LpTap<I, 5> {
    static __device__ __forceinline__ void run(const float (&)[12], float (&)[4]) {}
};

#define XG4 (W/4)   // 96 groups per row
__global__ __launch_bounds__(256) void lp_stage_kernel(const float* __restrict__ xin,
                                                       float* __restrict__ dout, int stage) {
    int gid = blockIdx.x * blockDim.x + threadIdx.x;
    int total = NIMG * H * XG4;
    if (gid >= total) return;
    int img = gid / (H * XG4);
    int rem = gid - img * (H * XG4);
    int y  = rem / XG4;
    int x4 = (rem - y * XG4) * 4;

    const float* cur  = (stage == 0) ? xin : g_lp[stage - 1];
    const float* base = cur + (size_t)img * HW;

    float acc[4] = {0.f, 0.f, 0.f, 0.f};
    if (y >= 2 && y <= H - 3 && x4 >= 4 && x4 <= W - 8) {
        const float* p = base + (size_t)y * W + x4;
        #pragma unroll
        for (int i = 0; i < 5; i++) {
            const float4* rp = (const float4*)(p + (i - 2) * W - 4);
            float r[12];
            #pragma unroll
            for (int q = 0; q < 3; q++) {
                float4 v = __ldg(&rp[q]);
                r[4*q] = v.x; r[4*q+1] = v.y; r[4*q+2] = v.z; r[4*q+3] = v.w;
            }
            switch (i) {
                case 0: LpTap<0,0>::run(r, acc); break;
                case 1: LpTap<1,0>::run(r, acc); break;
                case 2: LpTap<2,0>::run(r, acc); break;
                case 3: LpTap<3,0>::run(r, acc); break;
                case 4: LpTap<4,0>::run(r, acc); break;
            }
        }
    } else {
        #pragma unroll
        for (int i = 0; i < 5; i++) {
            int yy = reflect_idx(y + i - 2, H);
            float r[12];
            #pragma unroll
            for (int u = 0; u < 12; u++) {
                int xx = reflect_idx(x4 + u - 4, W);   // r[u] = px at x4 + u - 4
                r[u] = __ldg(base + yy*W + xx);
            }
            switch (i) {
                case 0: LpTap<0,0>::run(r, acc); break;
                case 1: LpTap<1,0>::run(r, acc); break;
                case 2: LpTap<2,0>::run(r, acc); break;
                case 3: LpTap<3,0>::run(r, acc); break;
                case 4: LpTap<4,0>::run(r, acc); break;
            }
        }
    }

    size_t p0 = (size_t)img * HW + (size_t)y * W + x4;
    float4 cv = *(const float4*)(base + (size_t)y * W + x4);
    *(float4*)&g_bp[stage][p0] =
        make_float4(cv.x - acc[0], cv.y - acc[1], cv.z - acc[2], cv.w - acc[3]);
    if (stage < 2) {
        *(float4*)&g_lp[stage][p0] = make_float4(acc[0], acc[1], acc[2], acc[3]);
    } else {
        int b = img / 3, c = img % 3;
        float* op = dout + (size_t)(b*87 + c*29 + 28) * HW + (size_t)y * W + x4;
        *(float4*)op = make_float4(acc[0], acc[1], acc[2], acc[3]);
    }
}

// =====================================================================
// Directional 15x15 conv — one (scale, direction) per kernel template,
// all 225 weights as FFMA immediates via template recursion.
// Tile 64x16, 256 threads, 4 px/thread.
// =====================================================================
#define DT_W 64
#define DT_H 16
#define DROWS 30       // DT_H + 14
#define DCOLS 78       // DT_W + 14
#define DSTR  80       // padded stride (16B aligned rows)

template<int S, int D, int ND, int KY, int KX>
struct KxLoop {
    static __device__ __forceinline__ void run(const float (&r)[20], float (&acc)[4]) {
        constexpr float w = Filt<S, D, ND>::f.w[KY*15 + KX];
        acc[0] = fmaf(r[KX + 0], w, acc[0]);
        acc[1] = fmaf(r[KX + 1], w, acc[1]);
        acc[2] = fmaf(r[KX + 2], w, acc[2]);
        acc[3] = fmaf(r[KX + 3], w, acc[3]);
        KxLoop<S, D, ND, KY, KX+1>::run(r, acc);
    }
};
template<int S, int D, int ND, int KY>
struct KxLoop<S, D, ND, KY, 15> {
    static __device__ __forceinline__ void run(const float (&)[20], float (&)[4]) {}
};

template<int S, int D, int ND, int KY>
struct KyLoop {
    static __device__ __forceinline__ void run(const float* sp, float (&acc)[4]) {
        float r[20];
        const float4* rp = (const float4*)(sp + KY * DSTR);
        #pragma unroll
        for (int q = 0; q < 5; q++) {
            float4 v = rp[q];
            r[4*q] = v.x; r[4*q+1] = v.y; r[4*q+2] = v.z; r[4*q+3] = v.w;
        }
        KxLoop<S, D, ND, KY, 0>::run(r, acc);
        KyLoop<S, D, ND, KY+1>::run(sp, acc);
    }
};
template<int S, int D, int ND>
struct KyLoop<S, D, ND, 15> {
    static __device__ __forceinline__ void run(const float*, float (&)[4]) {}
};

template<int S, int D, int ND, int CH>
__global__ __launch_bounds__(256) void dir_conv_kernel(float* __restrict__ dout) {
    __shared__ float s_in[DROWS * DSTR];

    int img = blockIdx.z;
    int x0 = blockIdx.x * DT_W;
    int y0 = blockIdx.y * DT_H;
    const float* bp = g_bp[S] + (size_t)img * HW;
    int tid = threadIdx.x;

    for (int i = tid; i < DROWS * DCOLS; i += 256) {
        int r = i / DCOLS, c = i - r * DCOLS;
        int gy = reflect_idx(y0 + r - 7, H);
        int gx = reflect_idx(x0 + c - 7, W);
        s_in[r * DSTR + c] = __ldg(bp + gy * W + gx);
    }
    __syncthreads();

    int tx = tid & 15;       // 16 x-groups of 4 px
    int ty = tid >> 4;       // 16 rows
    const float* sp = &s_in[ty * DSTR + tx * 4];

    float acc[4] = {0.f, 0.f, 0.f, 0.f};
    KyLoop<S, D, ND, 0>::run(sp, acc);

    int b = img / 3, c = img % 3;
    float* op = dout + (size_t)(b*87 + c*29 + CH) * HW
                     + (size_t)(y0 + ty) * W + x0 + tx * 4;
    *(float4*)op = make_float4(acc[0], acc[1], acc[2], acc[3]);
}

// ---------------- launch ----------------
extern "C" void kernel_launch(void* const* d_in, const int* in_sizes, int n_in,
                              void* d_out, int out_size) {
    const float* x = (const float*)d_in[0];
    float* out = (float*)d_out;

    int groups = NIMG * H * XG4;
    int blocks = (groups + 255) / 256;
    lp_stage_kernel<<<blocks, 256>>>(x, out, 0);
    lp_stage_kernel<<<blocks, 256>>>(x, out, 1);
    lp_stage_kernel<<<blocks, 256>>>(x, out, 2);

    dim3 grid(W / DT_W, H / DT_H, NIMG);   // 6 x 24 x 24

#define LAUNCH_DIR(S, D, ND, FB) \
    dir_conv_kernel<S, D, ND, (FB) + (D)><<<grid, 256>>>(out)

    // scale 0: 4 dirs, channels 0..3
    LAUNCH_DIR(0, 0, 4, 0);  LAUNCH_DIR(0, 1, 4, 0);
    LAUNCH_DIR(0, 2, 4, 0);  LAUNCH_DIR(0, 3, 4, 0);
    // scale 1: 8 dirs, channels 4..11
    LAUNCH_DIR(1, 0, 8, 4);  LAUNCH_DIR(1, 1, 8, 4);
    LAUNCH_DIR(1, 2, 8, 4);  LAUNCH_DIR(1, 3, 8, 4);
    LAUNCH_DIR(1, 4, 8, 4);  LAUNCH_DIR(1, 5, 8, 4);
    LAUNCH_DIR(1, 6, 8, 4);  LAUNCH_DIR(1, 7, 8, 4);
    // scale 2: 16 dirs, channels 12..27
    LAUNCH_DIR(2, 0, 16, 12);  LAUNCH_DIR(2, 1, 16, 12);
    LAUNCH_DIR(2, 2, 16, 12);  LAUNCH_DIR(2, 3, 16, 12);
    LAUNCH_DIR(2, 4, 16, 12);  LAUNCH_DIR(2, 5, 16, 12);
    LAUNCH_DIR(2, 6, 16, 12);  LAUNCH_DIR(2, 7, 16, 12);
    LAUNCH_DIR(2, 8, 16, 12);  LAUNCH_DIR(2, 9, 16, 12);
    LAUNCH_DIR(2, 10, 16, 12); LAUNCH_DIR(2, 11, 16, 12);
    LAUNCH_DIR(2, 12, 16, 12); LAUNCH_DIR(2, 13, 16, 12);
    LAUNCH_DIR(2, 14, 16, 12); LAUNCH_DIR(2, 15, 16, 12);
#undef LAUNCH_DIR
}

// round 6
// speedup vs baseline: 2.0953x; 1.2859x over previous
#include <cuda_runtime.h>
#include <math.h>

#define W 384
#define H 384
#define HW (W*H)
#define NIMG 24

// ---------------- scratch (no allocations allowed) ----------------
__device__ float g_bp[3][NIMG*HW];        // bandpasses
__device__ float g_lp[2][NIMG*HW];        // intermediate lowpasses

// =====================================================================
// Compile-time double-precision math (matches numpy float64 to ~1e-15)
// =====================================================================
constexpr double PI_ = 3.14159265358979323846264338327950288;

constexpr double cexp(double x) {
    const double LN2 = 0.69314718055994530941723212145817657;
    int n = (int)(x / LN2 + (x >= 0 ? 0.5 : -0.5));
    double r = x - (double)n * LN2;
    double t = 1.0, term = 1.0;
    for (int i = 1; i <= 22; i++) { term *= r / (double)i; t += term; }
    double s = 1.0;
    if (n >= 0) for (int i = 0; i < n; i++)  s *= 2.0;
    else        for (int i = 0; i < -n; i++) s *= 0.5;
    return t * s;
}
constexpr double ccos(double x) {   // x in [0, pi)
    double t = x; bool neg = false;
    if (t > PI_ * 0.5) { t = PI_ - t; neg = true; }
    double t2 = t*t, term = 1.0, s = 1.0;
    for (int i = 1; i <= 16; i++) { term *= -t2 / (double)((2*i-1)*(2*i)); s += term; }
    return neg ? -s : s;
}
constexpr double csin(double x) {   // x in [0, pi)
    double t = x;
    if (t > PI_ * 0.5) t = PI_ - t;
    double t2 = t*t, term = t, s = t;
    for (int i = 1; i <= 16; i++) { term *= -t2 / (double)((2*i)*(2*i+1)); s += term; }
    return s;
}
constexpr double csqrt(double x) {
    if (x <= 0.0) return 0.0;
    double y = (x > 1.0) ? x : 1.0;
    for (int i = 0; i < 80; i++) y = 0.5 * (y + x / y);
    return y;
}

// ---------------- oriented 15x15 filters, computed at compile time ----------------
struct F225 { float w[225]; };

constexpr F225 make_filt(int s, int d, int nd) {
    double scale = (double)(s + 1);
    double sx = 2.0 * scale, sy = 0.5 * scale;
    double ang = PI_ * (double)d / (double)nd;
    double ca = ccos(ang), sa = csin(ang);
    double k[225] = {};
    double sum = 0.0;
    for (int i = 0; i < 15; i++) {
        for (int j = 0; j < 15; j++) {
            double X = (double)(j - 7), Y = (double)(i - 7);
            double Xr = X * ca - Y * sa;
            double Yr = X * sa + Y * ca;
            double v = cexp(-0.5 * (Xr*Xr/(sx*sx) + Yr*Yr/(sy*sy))) * Xr / (sx*sx);
            k[i*15 + j] = v;
            sum += v;
        }
    }
    double mean = sum / 225.0;
    double nr = 0.0;
    for (int i = 0; i < 225; i++) { k[i] -= mean; nr += k[i]*k[i]; }
    nr = csqrt(nr);
    double inv = (nr > 1e-6) ? 1.0 / nr : 1.0;
    F225 f{};
    for (int i = 0; i < 225; i++) f.w[i] = (float)(k[i] * inv);
    return f;
}

template<int S, int D, int ND>
struct Filt { static constexpr F225 f = make_filt(S, D, ND); };
template<int S, int D, int ND> constexpr F225 Filt<S, D, ND>::f;

// ---------------- 5x5 gaussian lowpass at compile time ----------------
struct F25 { float w[25]; };
constexpr F25 make_lp() {
    double g[5] = {}; double s1 = 0.0;
    for (int i = 0; i < 5; i++) { double a = (double)(i - 2); g[i] = cexp(-0.5*a*a); s1 += g[i]; }
    double k1[5] = {};
    for (int i = 0; i < 5; i++) k1[i] = g[i] / s1;
    double k2[25] = {}; double s2 = 0.0;
    for (int i = 0; i < 5; i++)
        for (int j = 0; j < 5; j++) { k2[i*5+j] = k1[i]*k1[j]; s2 += k2[i*5+j]; }
    F25 f{};
    for (int i = 0; i < 25; i++) f.w[i] = (float)(k2[i] / s2);
    return f;
}
struct LPF { static constexpr F25 f = make_lp(); };
constexpr F25 LPF::f;

__device__ __forceinline__ int reflect_idx(int i, int n) {
    if (i < 0) return -i;
    if (i >= n) return 2*n - 2 - i;
    return i;
}

// =====================================================================
// Laplacian pyramid stage (immediate-weight 5x5), 4 px/thread
// Convention (both paths): r[u] = pixel at x4 + u - 4
// =====================================================================
template<int I, int J>
struct LpTap {
    static __device__ __forceinline__ void run(const float (&r)[12], float (&acc)[4]) {
        constexpr float w = LPF::f.w[I*5 + J];
        acc[0] = fmaf(r[2 + J + 0], w, acc[0]);
        acc[1] = fmaf(r[2 + J + 1], w, acc[1]);
        acc[2] = fmaf(r[2 + J + 2], w, acc[2]);
        acc[3] = fmaf(r[2 + J + 3], w, acc[3]);
        LpTap<I, J+1>::run(r, acc);
    }
};
template<int I> struct LpTap<I, 5> {
    static __device__ __forceinline__ void run(const float (&)[12], float (&)[4]) {}
};

#define XG4 (W/4)   // 96 groups per row
__global__ __launch_bounds__(256) void lp_stage_kernel(const float* __restrict__ xin,
                                                       float* __restrict__ dout, int stage) {
    int gid = blockIdx.x * blockDim.x + threadIdx.x;
    int total = NIMG * H * XG4;
    if (gid >= total) return;
    int img = gid / (H * XG4);
    int rem = gid - img * (H * XG4);
    int y  = rem / XG4;
    int x4 = (rem - y * XG4) * 4;

    const float* cur  = (stage == 0) ? xin : g_lp[stage - 1];
    const float* base = cur + (size_t)img * HW;

    float acc[4] = {0.f, 0.f, 0.f, 0.f};
    if (y >= 2 && y <= H - 3 && x4 >= 4 && x4 <= W - 8) {
        const float* p = base + (size_t)y * W + x4;
        #pragma unroll
        for (int i = 0; i < 5; i++) {
            const float4* rp = (const float4*)(p + (i - 2) * W - 4);
            float r[12];
            #pragma unroll
            for (int q = 0; q < 3; q++) {
                float4 v = __ldg(&rp[q]);
                r[4*q] = v.x; r[4*q+1] = v.y; r[4*q+2] = v.z; r[4*q+3] = v.w;
            }
            switch (i) {
                case 0: LpTap<0,0>::run(r, acc); break;
                case 1: LpTap<1,0>::run(r, acc); break;
                case 2: LpTap<2,0>::run(r, acc); break;
                case 3: LpTap<3,0>::run(r, acc); break;
                case 4: LpTap<4,0>::run(r, acc); break;
            }
        }
    } else {
        #pragma unroll
        for (int i = 0; i < 5; i++) {
            int yy = reflect_idx(y + i - 2, H);
            float r[12];
            #pragma unroll
            for (int u = 0; u < 12; u++) {
                int xx = reflect_idx(x4 + u - 4, W);
                r[u] = __ldg(base + yy*W + xx);
            }
            switch (i) {
                case 0: LpTap<0,0>::run(r, acc); break;
                case 1: LpTap<1,0>::run(r, acc); break;
                case 2: LpTap<2,0>::run(r, acc); break;
                case 3: LpTap<3,0>::run(r, acc); break;
                case 4: LpTap<4,0>::run(r, acc); break;
            }
        }
    }

    size_t p0 = (size_t)img * HW + (size_t)y * W + x4;
    float4 cv = *(const float4*)(base + (size_t)y * W + x4);
    *(float4*)&g_bp[stage][p0] =
        make_float4(cv.x - acc[0], cv.y - acc[1], cv.z - acc[2], cv.w - acc[3]);
    if (stage < 2) {
        *(float4*)&g_lp[stage][p0] = make_float4(acc[0], acc[1], acc[2], acc[3]);
    } else {
        int b = img / 3, c = img % 3;
        float* op = dout + (size_t)(b*87 + c*29 + 28) * HW + (size_t)y * W + x4;
        *(float4*)op = make_float4(acc[0], acc[1], acc[2], acc[3]);
    }
}

// =====================================================================
// Directional 15x15 conv — 4 directions per block, weights as FFMA
// immediates. Tile 64x32, 256 threads, 8 px/thread, conflict-free LDS.
// =====================================================================
#define DT_W 64
#define DT_H 32
#define DROWS 46       // DT_H + 14
#define DCOLS 78       // DT_W + 14
#define DSTR  84       // row stride in floats: 84%32=20 -> 8 consecutive
                       // rows hit distinct bank groups; 336B keeps float4 align

template<int S, int D, int ND, int KY, int KX>
struct Kx8 {
    static __device__ __forceinline__ void run(const float (&r)[24], float* acc) {
        constexpr float w = Filt<S, D, ND>::f.w[KY*15 + KX];
        #pragma unroll
        for (int t = 0; t < 8; t++)
            acc[t] = fmaf(r[KX + t], w, acc[t]);
        Kx8<S, D, ND, KY, KX+1>::run(r, acc);
    }
};
template<int S, int D, int ND, int KY>
struct Kx8<S, D, ND, KY, 15> {
    static __device__ __forceinline__ void run(const float (&)[24], float*) {}
};

template<int S, int D0, int ND, int KY>
struct Ky4 {
    static __device__ __forceinline__ void run(const float* sp, float (&acc)[4][8]) {
        float r[24];
        const float4* rp = (const float4*)(sp + KY * DSTR);
        #pragma unroll
        for (int q = 0; q < 6; q++) {
            float4 v = rp[q];
            r[4*q] = v.x; r[4*q+1] = v.y; r[4*q+2] = v.z; r[4*q+3] = v.w;
        }
        Kx8<S, D0+0, ND, KY, 0>::run(r, acc[0]);
        Kx8<S, D0+1, ND, KY, 0>::run(r, acc[1]);
        Kx8<S, D0+2, ND, KY, 0>::run(r, acc[2]);
        Kx8<S, D0+3, ND, KY, 0>::run(r, acc[3]);
        Ky4<S, D0, ND, KY+1>::run(sp, acc);
    }
};
template<int S, int D0, int ND>
struct Ky4<S, D0, ND, 15> {
    static __device__ __forceinline__ void run(const float*, float (&)[4][8]) {}
};

template<int S, int D0, int ND, int CH0>
__global__ __launch_bounds__(256) void dir_conv4_kernel(float* __restrict__ dout) {
    __shared__ float s_in[DROWS * DSTR];   // 46*84*4 = 15456 B

    int img = blockIdx.z;
    int x0 = blockIdx.x * DT_W;
    int y0 = blockIdx.y * DT_H;
    const float* bp = g_bp[S] + (size_t)img * HW;
    int tid = threadIdx.x;

    for (int i = tid; i < DROWS * DCOLS; i += 256) {
        int r = i / DCOLS, c = i - r * DCOLS;
        int gy = reflect_idx(y0 + r - 7, H);
        int gx = reflect_idx(x0 + c - 7, W);
        s_in[r * DSTR + c] = __ldg(bp + gy * W + gx);
    }
    __syncthreads();

    // conflict-free mapping: 8 consecutive lanes = 8 consecutive rows
    int sub = tid & 7;             // row within 8-group
    int xg  = (tid >> 3) & 7;      // 8 x-groups of 8 px
    int rg  = tid >> 6;            // 4 row-groups
    int ty  = rg * 8 + sub;        // 0..31
    const float* sp = &s_in[ty * DSTR + xg * 8];

    float acc[4][8];
    #pragma unroll
    for (int d = 0; d < 4; d++)
        #pragma unroll
        for (int t = 0; t < 8; t++) acc[d][t] = 0.f;

    Ky4<S, D0, ND, 0>::run(sp, acc);

    int b = img / 3, c = img % 3;
    size_t outoff = (size_t)(y0 + ty) * W + x0 + xg * 8;
    float* obase = dout + (size_t)(b*87 + c*29 + CH0) * HW + outoff;
    #pragma unroll
    for (int d = 0; d < 4; d++) {
        float* op = obase + (size_t)d * HW;
        ((float4*)op)[0] = make_float4(acc[d][0], acc[d][1], acc[d][2], acc[d][3]);
        ((float4*)op)[1] = make_float4(acc[d][4], acc[d][5], acc[d][6], acc[d][7]);
    }
}

// ---------------- launch ----------------
extern "C" void kernel_launch(void* const* d_in, const int* in_sizes, int n_in,
                              void* d_out, int out_size) {
    const float* x = (const float*)d_in[0];
    float* out = (float*)d_out;

    int groups = NIMG * H * XG4;
    int blocks = (groups + 255) / 256;
    lp_stage_kernel<<<blocks, 256>>>(x, out, 0);
    lp_stage_kernel<<<blocks, 256>>>(x, out, 1);
    lp_stage_kernel<<<blocks, 256>>>(x, out, 2);

    dim3 grid(W / DT_W, H / DT_H, NIMG);   // 6 x 12 x 24

    // scale 0: dirs 0..3 -> channels 0..3
    dir_conv4_kernel<0, 0, 4, 0><<<grid, 256>>>(out);
    // scale 1: dirs 0..7 -> channels 4..11
    dir_conv4_kernel<1, 0, 8, 4><<<grid, 256>>>(out);
    dir_conv4_kernel<1, 4, 8, 8><<<grid, 256>>>(out);
    // scale 2: dirs 0..15 -> channels 12..27
    dir_conv4_kernel<2, 0,  16, 12><<<grid, 256>>>(out);
    dir_conv4_kernel<2, 4,  16, 16><<<grid, 256>>>(out);
    dir_conv4_kernel<2, 8,  16, 20><<<grid, 256>>>(out);
    dir_conv4_kernel<2, 12, 16, 24><<<grid, 256>>>(out);
}

// round 7
// speedup vs baseline: 2.9876x; 1.4258x over previous
#include <cuda_runtime.h>
#include <math.h>

#define W 384
#define H 384
#define HW (W*H)
#define NIMG 24

// ---------------- scratch (no allocations allowed) ----------------
__device__ float g_bp[3][NIMG*HW];        // bandpasses
__device__ float g_lp[2][NIMG*HW];        // intermediate lowpasses

// =====================================================================
// Compile-time double-precision math (matches numpy float64 to ~1e-15)
// =====================================================================
constexpr double PI_ = 3.14159265358979323846264338327950288;

constexpr double cexp(double x) {
    const double LN2 = 0.69314718055994530941723212145817657;
    int n = (int)(x / LN2 + (x >= 0 ? 0.5 : -0.5));
    double r = x - (double)n * LN2;
    double t = 1.0, term = 1.0;
    for (int i = 1; i <= 22; i++) { term *= r / (double)i; t += term; }
    double s = 1.0;
    if (n >= 0) for (int i = 0; i < n; i++)  s *= 2.0;
    else        for (int i = 0; i < -n; i++) s *= 0.5;
    return t * s;
}
constexpr double ccos(double x) {   // x in [0, pi)
    double t = x; bool neg = false;
    if (t > PI_ * 0.5) { t = PI_ - t; neg = true; }
    double t2 = t*t, term = 1.0, s = 1.0;
    for (int i = 1; i <= 16; i++) { term *= -t2 / (double)((2*i-1)*(2*i)); s += term; }
    return neg ? -s : s;
}
constexpr double csin(double x) {   // x in [0, pi)
    double t = x;
    if (t > PI_ * 0.5) t = PI_ - t;
    double t2 = t*t, term = t, s = t;
    for (int i = 1; i <= 16; i++) { term *= -t2 / (double)((2*i)*(2*i+1)); s += term; }
    return s;
}
constexpr double csqrt(double x) {
    if (x <= 0.0) return 0.0;
    double y = (x > 1.0) ? x : 1.0;
    for (int i = 0; i < 80; i++) y = 0.5 * (y + x / y);
    return y;
}

// ---------------- oriented 15x15 filters, computed at compile time ----------------
struct F225 { float w[225]; };

constexpr F225 make_filt(int s, int d, int nd) {
    double scale = (double)(s + 1);
    double sx = 2.0 * scale, sy = 0.5 * scale;
    double ang = PI_ * (double)d / (double)nd;
    double ca = ccos(ang), sa = csin(ang);
    double k[225] = {};
    double sum = 0.0;
    for (int i = 0; i < 15; i++) {
        for (int j = 0; j < 15; j++) {
            double X = (double)(j - 7), Y = (double)(i - 7);
            double Xr = X * ca - Y * sa;
            double Yr = X * sa + Y * ca;
            double v = cexp(-0.5 * (Xr*Xr/(sx*sx) + Yr*Yr/(sy*sy))) * Xr / (sx*sx);
            k[i*15 + j] = v;
            sum += v;
        }
    }
    double mean = sum / 225.0;
    double nr = 0.0;
    for (int i = 0; i < 225; i++) { k[i] -= mean; nr += k[i]*k[i]; }
    nr = csqrt(nr);
    double inv = (nr > 1e-6) ? 1.0 / nr : 1.0;
    F225 f{};
    for (int i = 0; i < 225; i++) f.w[i] = (float)(k[i] * inv);
    return f;
}

template<int S, int D, int ND>
struct Filt { static constexpr F225 f = make_filt(S, D, ND); };
template<int S, int D, int ND> constexpr F225 Filt<S, D, ND>::f;

// ---------------- 5x5 gaussian lowpass at compile time ----------------
struct F25 { float w[25]; };
constexpr F25 make_lp() {
    double g[5] = {}; double s1 = 0.0;
    for (int i = 0; i < 5; i++) { double a = (double)(i - 2); g[i] = cexp(-0.5*a*a); s1 += g[i]; }
    double k1[5] = {};
    for (int i = 0; i < 5; i++) k1[i] = g[i] / s1;
    double k2[25] = {}; double s2 = 0.0;
    for (int i = 0; i < 5; i++)
        for (int j = 0; j < 5; j++) { k2[i*5+j] = k1[i]*k1[j]; s2 += k2[i*5+j]; }
    F25 f{};
    for (int i = 0; i < 25; i++) f.w[i] = (float)(k2[i] / s2);
    return f;
}
struct LPF { static constexpr F25 f = make_lp(); };
constexpr F25 LPF::f;

__device__ __forceinline__ int reflect_idx(int i, int n) {
    if (i < 0) return -i;
    if (i >= n) return 2*n - 2 - i;
    return i;
}

// =====================================================================
// Laplacian pyramid stage (immediate-weight 5x5), 4 px/thread
// Convention (both paths): r[u] = pixel at x4 + u - 4
// =====================================================================
template<int I, int J>
struct LpTap {
    static __device__ __forceinline__ void run(const float (&r)[12], float (&acc)[4]) {
        constexpr float w = LPF::f.w[I*5 + J];
        acc[0] = fmaf(r[2 + J + 0], w, acc[0]);
        acc[1] = fmaf(r[2 + J + 1], w, acc[1]);
        acc[2] = fmaf(r[2 + J + 2], w, acc[2]);
        acc[3] = fmaf(r[2 + J + 3], w, acc[3]);
        LpTap<I, J+1>::run(r, acc);
    }
};
template<int I> struct LpTap<I, 5> {
    static __device__ __forceinline__ void run(const float (&)[12], float (&)[4]) {}
};

#define XG4 (W/4)   // 96 groups per row
__global__ __launch_bounds__(256) void lp_stage_kernel(const float* __restrict__ xin,
                                                       float* __restrict__ dout, int stage) {
    int gid = blockIdx.x * blockDim.x + threadIdx.x;
    int total = NIMG * H * XG4;
    if (gid >= total) return;
    int img = gid / (H * XG4);
    int rem = gid - img * (H * XG4);
    int y  = rem / XG4;
    int x4 = (rem - y * XG4) * 4;

    const float* cur  = (stage == 0) ? xin : g_lp[stage - 1];
    const float* base = cur + (size_t)img * HW;

    float acc[4] = {0.f, 0.f, 0.f, 0.f};
    if (y >= 2 && y <= H - 3 && x4 >= 4 && x4 <= W - 8) {
        const float* p = base + (size_t)y * W + x4;
        #pragma unroll
        for (int i = 0; i < 5; i++) {
            const float4* rp = (const float4*)(p + (i - 2) * W - 4);
            float r[12];
            #pragma unroll
            for (int q = 0; q < 3; q++) {
                float4 v = __ldg(&rp[q]);
                r[4*q] = v.x; r[4*q+1] = v.y; r[4*q+2] = v.z; r[4*q+3] = v.w;
            }
            switch (i) {
                case 0: LpTap<0,0>::run(r, acc); break;
                case 1: LpTap<1,0>::run(r, acc); break;
                case 2: LpTap<2,0>::run(r, acc); break;
                case 3: LpTap<3,0>::run(r, acc); break;
                case 4: LpTap<4,0>::run(r, acc); break;
            }
        }
    } else {
        #pragma unroll
        for (int i = 0; i < 5; i++) {
            int yy = reflect_idx(y + i - 2, H);
            float r[12];
            #pragma unroll
            for (int u = 0; u < 12; u++) {
                int xx = reflect_idx(x4 + u - 4, W);
                r[u] = __ldg(base + yy*W + xx);
            }
            switch (i) {
                case 0: LpTap<0,0>::run(r, acc); break;
                case 1: LpTap<1,0>::run(r, acc); break;
                case 2: LpTap<2,0>::run(r, acc); break;
                case 3: LpTap<3,0>::run(r, acc); break;
                case 4: LpTap<4,0>::run(r, acc); break;
            }
        }
    }

    size_t p0 = (size_t)img * HW + (size_t)y * W + x4;
    float4 cv = *(const float4*)(base + (size_t)y * W + x4);
    *(float4*)&g_bp[stage][p0] =
        make_float4(cv.x - acc[0], cv.y - acc[1], cv.z - acc[2], cv.w - acc[3]);
    if (stage < 2) {
        *(float4*)&g_lp[stage][p0] = make_float4(acc[0], acc[1], acc[2], acc[3]);
    } else {
        int b = img / 3, c = img % 3;
        float* op = dout + (size_t)(b*87 + c*29 + 28) * HW + (size_t)y * W + x4;
        *(float4*)op = make_float4(acc[0], acc[1], acc[2], acc[3]);
    }
}

// =====================================================================
// Directional 15x15 conv — 4 dirs/block using filter point-antisymmetry:
//   w[14-ky][14-kx] = -w[ky][kx]   (exact to ~1e-16; w[7][7] ~ 0)
// Per tap-pair: 1 shared difference + 4 FMAs (vs 8 FMAs).
// Tile 64x16, 256 threads, 4 px/thread.
// =====================================================================
#define DT_W 64
#define DT_H 16
#define DROWS 30       // DT_H + 14
#define DCOLS 78       // DT_W + 14
#define DSTR  84       // 84%32=20 -> 8 consecutive rows hit distinct banks

// paired rows ky<7 with 14-ky
template<int S, int D0, int ND, int KY, int KX>
struct KxP {
    static __device__ __forceinline__ void run(const float (&rA)[20], const float (&rB)[20],
                                               float (&acc)[4][4]) {
        float d[4];
        #pragma unroll
        for (int t = 0; t < 4; t++)
            d[t] = rA[KX + t] - rB[14 - KX + t];
        constexpr float w0 = Filt<S, D0+0, ND>::f.w[KY*15 + KX];
        constexpr float w1 = Filt<S, D0+1, ND>::f.w[KY*15 + KX];
        constexpr float w2 = Filt<S, D0+2, ND>::f.w[KY*15 + KX];
        constexpr float w3 = Filt<S, D0+3, ND>::f.w[KY*15 + KX];
        #pragma unroll
        for (int t = 0; t < 4; t++) {
            acc[0][t] = fmaf(d[t], w0, acc[0][t]);
            acc[1][t] = fmaf(d[t], w1, acc[1][t]);
            acc[2][t] = fmaf(d[t], w2, acc[2][t]);
            acc[3][t] = fmaf(d[t], w3, acc[3][t]);
        }
        KxP<S, D0, ND, KY, KX+1>::run(rA, rB, acc);
    }
};
template<int S, int D0, int ND, int KY>
struct KxP<S, D0, ND, KY, 15> {
    static __device__ __forceinline__ void run(const float (&)[20], const float (&)[20],
                                               float (&)[4][4]) {}
};

// center row (ky=7): kx pairs with 14-kx within the row; kx=7 weight ~0, skipped
template<int S, int D0, int ND, int KX>
struct KxC {
    static __device__ __forceinline__ void run(const float (&r)[20], float (&acc)[4][4]) {
        float d[4];
        #pragma unroll
        for (int t = 0; t < 4; t++)
            d[t] = r[KX + t] - r[14 - KX + t];
        constexpr float w0 = Filt<S, D0+0, ND>::f.w[7*15 + KX];
        constexpr float w1 = Filt<S, D0+1, ND>::f.w[7*15 + KX];
        constexpr float w2 = Filt<S, D0+2, ND>::f.w[7*15 + KX];
        constexpr float w3 = Filt<S, D0+3, ND>::f.w[7*15 + KX];
        #pragma unroll
        for (int t = 0; t < 4; t++) {
            acc[0][t] = fmaf(d[t], w0, acc[0][t]);
            acc[1][t] = fmaf(d[t], w1, acc[1][t]);
            acc[2][t] = fmaf(d[t], w2, acc[2][t]);
            acc[3][t] = fmaf(d[t], w3, acc[3][t]);
        }
        KxC<S, D0, ND, KX+1>::run(r, acc);
    }
};
template<int S, int D0, int ND>
struct KxC<S, D0, ND, 7> {
    static __device__ __forceinline__ void run(const float (&)[20], float (&)[4][4]) {}
};

template<int S, int D0, int ND, int KY>
struct RowP {
    static __device__ __forceinline__ void run(const float* sp, float (&acc)[4][4]) {
        float rA[20], rB[20];
        const float4* pa = (const float4*)(sp + KY * DSTR);
        const float4* pb = (const float4*)(sp + (14 - KY) * DSTR);
        #pragma unroll
        for (int q = 0; q < 5; q++) {
            float4 a = pa[q];
            rA[4*q] = a.x; rA[4*q+1] = a.y; rA[4*q+2] = a.z; rA[4*q+3] = a.w;
            float4 b = pb[q];
            rB[4*q] = b.x; rB[4*q+1] = b.y; rB[4*q+2] = b.z; rB[4*q+3] = b.w;
        }
        KxP<S, D0, ND, KY, 0>::run(rA, rB, acc);
        RowP<S, D0, ND, KY+1>::run(sp, acc);
    }
};
template<int S, int D0, int ND>
struct RowP<S, D0, ND, 7> {
    static __device__ __forceinline__ void run(const float* sp, float (&acc)[4][4]) {
        float r[20];
        const float4* pa = (const float4*)(sp + 7 * DSTR);
        #pragma unroll
        for (int q = 0; q < 5; q++) {
            float4 a = pa[q];
            r[4*q] = a.x; r[4*q+1] = a.y; r[4*q+2] = a.z; r[4*q+3] = a.w;
        }
        KxC<S, D0, ND, 0>::run(r, acc);
    }
};

template<int S, int D0, int ND, int CH0>
__global__ __launch_bounds__(256) void dir_conv4_kernel(float* __restrict__ dout) {
    __shared__ float s_in[DROWS * DSTR];   // 30*84*4 = 10080 B

    int img = blockIdx.z;
    int x0 = blockIdx.x * DT_W;
    int y0 = blockIdx.y * DT_H;
    const float* bp = g_bp[S] + (size_t)img * HW;
    int tid = threadIdx.x;

    for (int i = tid; i < DROWS * DCOLS; i += 256) {
        int r = i / DCOLS, c = i - r * DCOLS;
        int gy = reflect_idx(y0 + r - 7, H);
        int gx = reflect_idx(x0 + c - 7, W);
        s_in[r * DSTR + c] = __ldg(bp + gy * W + gx);
    }
    __syncthreads();

    // 8 consecutive lanes = 8 consecutive rows (conflict-free)
    int sub = tid & 7;             // row within 8-group
    int xg  = (tid >> 3) & 15;     // 16 x-groups of 4 px
    int rg  = tid >> 7;            // 2 row-groups
    int ty  = rg * 8 + sub;        // 0..15
    const float* sp = &s_in[ty * DSTR + xg * 4];

    float acc[4][4];
    #pragma unroll
    for (int d = 0; d < 4; d++)
        #pragma unroll
        for (int t = 0; t < 4; t++) acc[d][t] = 0.f;

    RowP<S, D0, ND, 0>::run(sp, acc);

    int b = img / 3, c = img % 3;
    size_t outoff = (size_t)(y0 + ty) * W + x0 + xg * 4;
    float* obase = dout + (size_t)(b*87 + c*29 + CH0) * HW + outoff;
    #pragma unroll
    for (int d = 0; d < 4; d++) {
        float* op = obase + (size_t)d * HW;
        *(float4*)op = make_float4(acc[d][0], acc[d][1], acc[d][2], acc[d][3]);
    }
}

// ---------------- launch ----------------
extern "C" void kernel_launch(void* const* d_in, const int* in_sizes, int n_in,
                              void* d_out, int out_size) {
    const float* x = (const float*)d_in[0];
    float* out = (float*)d_out;

    int groups = NIMG * H * XG4;
    int blocks = (groups + 255) / 256;
    lp_stage_kernel<<<blocks, 256>>>(x, out, 0);
    lp_stage_kernel<<<blocks, 256>>>(x, out, 1);
    lp_stage_kernel<<<blocks, 256>>>(x, out, 2);

    dim3 grid(W / DT_W, H / DT_H, NIMG);   // 6 x 24 x 24

    // scale 0: dirs 0..3 -> channels 0..3
    dir_conv4_kernel<0, 0, 4, 0><<<grid, 256>>>(out);
    // scale 1: dirs 0..7 -> channels 4..11
    dir_conv4_kernel<1, 0, 8, 4><<<grid, 256>>>(out);
    dir_conv4_kernel<1, 4, 8, 8><<<grid, 256>>>(out);
    // scale 2: dirs 0..15 -> channels 12..27
    dir_conv4_kernel<2, 0,  16, 12><<<grid, 256>>>(out);
    dir_conv4_kernel<2, 4,  16, 16><<<grid, 256>>>(out);
    dir_conv4_kernel<2, 8,  16, 20><<<grid, 256>>>(out);
    dir_conv4_kernel<2, 12, 16, 24><<<grid, 256>>>(out);
}

// round 9
// speedup vs baseline: 3.7732x; 1.2629x over previous
#include <cuda_runtime.h>
#include <math.h>

#define W 384
#define H 384
#define HW (W*H)
#define NIMG 24

#define TAU 1e-6f

// ---------------- scratch (no allocations allowed) ----------------
__device__ float g_bp[3][NIMG*HW];        // bandpasses

// =====================================================================
// Compile-time double-precision math (matches numpy float64 to ~1e-15)
// =====================================================================
constexpr double PI_ = 3.14159265358979323846264338327950288;

constexpr double cexp(double x) {
    const double LN2 = 0.69314718055994530941723212145817657;
    int n = (int)(x / LN2 + (x >= 0 ? 0.5 : -0.5));
    double r = x - (double)n * LN2;
    double t = 1.0, term = 1.0;
    for (int i = 1; i <= 22; i++) { term *= r / (double)i; t += term; }
    double s = 1.0;
    if (n >= 0) for (int i = 0; i < n; i++)  s *= 2.0;
    else        for (int i = 0; i < -n; i++) s *= 0.5;
    return t * s;
}
constexpr double ccos(double x) {
    double t = x; bool neg = false;
    if (t > PI_ * 0.5) { t = PI_ - t; neg = true; }
    double t2 = t*t, term = 1.0, s = 1.0;
    for (int i = 1; i <= 16; i++) { term *= -t2 / (double)((2*i-1)*(2*i)); s += term; }
    return neg ? -s : s;
}
constexpr double csin(double x) {
    double t = x;
    if (t > PI_ * 0.5) t = PI_ - t;
    double t2 = t*t, term = t, s = t;
    for (int i = 1; i <= 16; i++) { term *= -t2 / (double)((2*i)*(2*i+1)); s += term; }
    return s;
}
constexpr double csqrt(double x) {
    if (x <= 0.0) return 0.0;
    double y = (x > 1.0) ? x : 1.0;
    for (int i = 0; i < 80; i++) y = 0.5 * (y + x / y);
    return y;
}

// ---------------- oriented 15x15 filters, computed at compile time ----------------
struct F225 { float w[225]; };

constexpr F225 make_filt(int s, int d, int nd) {
    double scale = (double)(s + 1);
    double sx = 2.0 * scale, sy = 0.5 * scale;
    double ang = PI_ * (double)d / (double)nd;
    double ca = ccos(ang), sa = csin(ang);
    double k[225] = {};
    double sum = 0.0;
    for (int i = 0; i < 15; i++) {
        for (int j = 0; j < 15; j++) {
            double X = (double)(j - 7), Y = (double)(i - 7);
            double Xr = X * ca - Y * sa;
            double Yr = X * sa + Y * ca;
            double v = cexp(-0.5 * (Xr*Xr/(sx*sx) + Yr*Yr/(sy*sy))) * Xr / (sx*sx);
            k[i*15 + j] = v;
            sum += v;
        }
    }
    double mean = sum / 225.0;
    double nr = 0.0;
    for (int i = 0; i < 225; i++) { k[i] -= mean; nr += k[i]*k[i]; }
    nr = csqrt(nr);
    double inv = (nr > 1e-6) ? 1.0 / nr : 1.0;
    F225 f{};
    for (int i = 0; i < 225; i++) f.w[i] = (float)(k[i] * inv);
    return f;
}

template<int S, int D, int ND>
struct Filt { static constexpr F225 f = make_filt(S, D, ND); };
template<int S, int D, int ND> constexpr F225 Filt<S, D, ND>::f;

// ---------------- 5x5 gaussian lowpass at compile time ----------------
struct F25 { float w[25]; };
constexpr F25 make_lp() {
    double g[5] = {}; double s1 = 0.0;
    for (int i = 0; i < 5; i++) { double a = (double)(i - 2); g[i] = cexp(-0.5*a*a); s1 += g[i]; }
    double k1[5] = {};
    for (int i = 0; i < 5; i++) k1[i] = g[i] / s1;
    double k2[25] = {}; double s2 = 0.0;
    for (int i = 0; i < 5; i++)
        for (int j = 0; j < 5; j++) { k2[i*5+j] = k1[i]*k1[j]; s2 += k2[i*5+j]; }
    F25 f{};
    for (int i = 0; i < 25; i++) f.w[i] = (float)(k2[i] / s2);
    return f;
}
struct LPF { static constexpr F25 f = make_lp(); };
constexpr F25 LPF::f;

__device__ __forceinline__ int reflect_idx(int i, int n) {
    if (i < 0) return -i;
    if (i >= n) return 2*n - 2 - i;
    return i;
}

// =====================================================================
// Fused 3-stage Laplacian pyramid: one kernel, all stages in smem.
// Symmetric Gaussian => conv on reflect-extended inputs == reflected
// outputs, so chaining inside the halo is exact.
// Tile 64x16 output, halo 6. b0:28x76  b1:24x72  b2:20x68
// =====================================================================
#define B0S 76
#define B1S 72
#define B2S 68

template<int SSTR, int I, int J>
struct C5 {
    static __device__ __forceinline__ void run(const float* src, float& a) {
        constexpr float w = LPF::f.w[I*5 + J];
        a = fmaf(src[I*SSTR + J], w, a);
        C5<SSTR, I, J+1>::run(src, a);
    }
};
template<int SSTR, int I> struct C5<SSTR, I, 5> {
    static __device__ __forceinline__ void run(const float* src, float& a) {
        C5<SSTR, I+1, 0>::run(src, a);
    }
};
template<int SSTR> struct C5<SSTR, 5, 0> {
    static __device__ __forceinline__ void run(const float*, float&) {}
};
template<int SSTR>
__device__ __forceinline__ float conv5(const float* src) {
    float a = 0.f;
    C5<SSTR, 0, 0>::run(src, a);
    return a;
}

__global__ __launch_bounds__(256) void lp_fused_kernel(const float* __restrict__ xin,
                                                       float* __restrict__ dout) {
    __shared__ float b0[28 * B0S];
    __shared__ float b1[24 * B1S];
    __shared__ float b2[20 * B2S];

    int img = blockIdx.z;
    int x0 = blockIdx.x * 64;
    int y0 = blockIdx.y * 16;
    const float* base = xin + (size_t)img * HW;
    int tid = threadIdx.x;

    for (int i = tid; i < 28 * B0S; i += 256) {
        int r = i / B0S, c = i - r * B0S;
        int gy = reflect_idx(y0 - 6 + r, H);
        int gx = reflect_idx(x0 - 6 + c, W);
        b0[i] = __ldg(base + gy * W + gx);
    }
    __syncthreads();

    // stage 1: lp1 over 24x72 region (image rows y0-4 .. y0+19)
    for (int i = tid; i < 24 * B1S; i += 256) {
        int r = i / B1S, c = i - r * B1S;
        b1[i] = conv5<B0S>(&b0[r * B0S + c]);
    }
    __syncthreads();

    // bp0 (center) + stage 2
    size_t pbase = (size_t)img * HW;
    {
        int i = tid;                       // 256 groups = 16 rows x 16 groups of 4 px
        int ty = i >> 4, tx4 = (i & 15) * 4;
        float v[4];
        #pragma unroll
        for (int t = 0; t < 4; t++)
            v[t] = b0[(ty+6)*B0S + tx4 + t + 6] - b1[(ty+4)*B1S + tx4 + t + 4];
        *(float4*)&g_bp[0][pbase + (size_t)(y0+ty)*W + x0 + tx4] =
            make_float4(v[0], v[1], v[2], v[3]);
    }
    for (int i = tid; i < 20 * B2S; i += 256) {
        int r = i / B2S, c = i - r * B2S;
        b2[i] = conv5<B1S>(&b1[r * B1S + c]);
    }
    __syncthreads();

    // bp1 + stage3 + bp2 + lowpass (center only)
    int b = img / 3, cc = img % 3;
    float* lpo = dout + (size_t)(b*87 + cc*29 + 28) * HW;
    for (int i = tid; i < 1024; i += 256) {
        int ty = i >> 6, tx = i & 63;
        size_t pix = (size_t)(y0+ty)*W + x0 + tx;
        size_t go = pbase + pix;
        float l1 = b1[(ty+4)*B1S + tx + 4];
        float l2 = b2[(ty+2)*B2S + tx + 2];
        g_bp[1][go] = l1 - l2;
        float l3 = conv5<B2S>(&b2[ty * B2S + tx]);
        g_bp[2][go] = l2 - l3;
        lpo[pix] = l3;
    }
}

// =====================================================================
// Directional 15x15 conv — NDIR dirs/block, antisymmetry + zero-skip.
// Tile 64x16, 256 threads, 4 px/thread.
// =====================================================================
#define DT_W 64
#define DT_H 16
#define DROWS 30
#define DCOLS 78
#define DSTR  84       // 84%32=20 -> 8 consecutive rows hit distinct banks

// any |w| significant across NDIR dirs at flat index I
template<int S, int D0, int ND, int NDIR, int I, int DD = 0>
struct AnySig {
    static constexpr float w = Filt<S, D0+DD, ND>::f.w[I];
    static constexpr bool v = (w > TAU || w < -TAU) || AnySig<S, D0, ND, NDIR, I, DD+1>::v;
};
template<int S, int D0, int ND, int NDIR, int I>
struct AnySig<S, D0, ND, NDIR, I, NDIR> { static constexpr bool v = false; };

// apply d[] to all NDIR accumulators with per-dir skip
template<int S, int D0, int ND, int NDIR, int I, int DD = 0>
struct FmaN {
    static __device__ __forceinline__ void run(const float (&d)[4], float (&acc)[NDIR][4]) {
        constexpr float w = Filt<S, D0+DD, ND>::f.w[I];
        if constexpr (w > TAU || w < -TAU) {
            #pragma unroll
            for (int t = 0; t < 4; t++)
                acc[DD][t] = fmaf(d[t], w, acc[DD][t]);
        }
        FmaN<S, D0, ND, NDIR, I, DD+1>::run(d, acc);
    }
};
template<int S, int D0, int ND, int NDIR, int I>
struct FmaN<S, D0, ND, NDIR, I, NDIR> {
    static __device__ __forceinline__ void run(const float (&)[4], float (&)[NDIR][4]) {}
};

// paired rows ky<7 with 14-ky
template<int S, int D0, int ND, int NDIR, int KY, int KX>
struct KxP {
    static __device__ __forceinline__ void run(const float (&rA)[20], const float (&rB)[20],
                                               float (&acc)[NDIR][4]) {
        if constexpr (AnySig<S, D0, ND, NDIR, KY*15 + KX>::v) {
            float d[4];
            #pragma unroll
            for (int t = 0; t < 4; t++)
                d[t] = rA[KX + t] - rB[14 - KX + t];
            FmaN<S, D0, ND, NDIR, KY*15 + KX>::run(d, acc);
        }
        KxP<S, D0, ND, NDIR, KY, KX+1>::run(rA, rB, acc);
    }
};
template<int S, int D0, int ND, int NDIR, int KY>
struct KxP<S, D0, ND, NDIR, KY, 15> {
    static __device__ __forceinline__ void run(const float (&)[20], const float (&)[20],
                                               float (&)[NDIR][4]) {}
};

// center row ky=7: kx pairs with 14-kx; kx=7 weight ~0, skipped
template<int S, int D0, int ND, int NDIR, int KX>
struct KxC {
    static __device__ __forceinline__ void run(const float (&r)[20], float (&acc)[NDIR][4]) {
        if constexpr (AnySig<S, D0, ND, NDIR, 7*15 + KX>::v) {
            float d[4];
            #pragma unroll
            for (int t = 0; t < 4; t++)
                d[t] = r[KX + t] - r[14 - KX + t];
            FmaN<S, D0, ND, NDIR, 7*15 + KX>::run(d, acc);
        }
        KxC<S, D0, ND, NDIR, KX+1>::run(r, acc);
    }
};
template<int S, int D0, int ND, int NDIR>
struct KxC<S, D0, ND, NDIR, 7> {
    static __device__ __forceinline__ void run(const float (&)[20], float (&)[NDIR][4]) {}
};

template<int S, int D0, int ND, int NDIR, int KY>
struct RowP {
    static __device__ __forceinline__ void run(const float* sp, float (&acc)[NDIR][4]) {
        float rA[20], rB[20];
        const float4* pa = (const float4*)(sp + KY * DSTR);
        const float4* pb = (const float4*)(sp + (14 - KY) * DSTR);
        #pragma unroll
        for (int q = 0; q < 5; q++) {
            float4 a = pa[q];
            rA[4*q] = a.x; rA[4*q+1] = a.y; rA[4*q+2] = a.z; rA[4*q+3] = a.w;
            float4 b = pb[q];
            rB[4*q] = b.x; rB[4*q+1] = b.y; rB[4*q+2] = b.z; rB[4*q+3] = b.w;
        }
        KxP<S, D0, ND, NDIR, KY, 0>::run(rA, rB, acc);
        RowP<S, D0, ND, NDIR, KY+1>::run(sp, acc);
    }
};
template<int S, int D0, int ND, int NDIR>
struct RowP<S, D0, ND, NDIR, 7> {
    static __device__ __forceinline__ void run(const float* sp, float (&acc)[NDIR][4]) {
        float r[20];
        const float4* pa = (const float4*)(sp + 7 * DSTR);
        #pragma unroll
        for (int q = 0; q < 5; q++) {
            float4 a = pa[q];
            r[4*q] = a.x; r[4*q+1] = a.y; r[4*q+2] = a.z; r[4*q+3] = a.w;
        }
        KxC<S, D0, ND, NDIR, 0>::run(r, acc);
    }
};

template<int S, int D0, int ND, int NDIR, int CH0>
__global__ __launch_bounds__(256) void dir_conv_kernel(float* __restrict__ dout) {
    __shared__ float s_in[DROWS * DSTR];

    int img = blockIdx.z;
    int x0 = blockIdx.x * DT_W;
    int y0 = blockIdx.y * DT_H;
    const float* bp = g_bp[S] + (size_t)img * HW;
    int tid = threadIdx.x;

    for (int i = tid; i < DROWS * DCOLS; i += 256) {
        int r = i / DCOLS, c = i - r * DCOLS;
        int gy = reflect_idx(y0 + r - 7, H);
        int gx = reflect_idx(x0 + c - 7, W);
        s_in[r * DSTR + c] = __ldg(bp + gy * W + gx);
    }
    __syncthreads();

    // 8 consecutive lanes = 8 consecutive rows (conflict-free)
    int sub = tid & 7;
    int xg  = (tid >> 3) & 15;     // 16 x-groups of 4 px
    int rg  = tid >> 7;            // 2 row-groups
    int ty  = rg * 8 + sub;        // 0..15
    const float* sp = &s_in[ty * DSTR + xg * 4];

    float acc[NDIR][4];
    #pragma unroll
    for (int d = 0; d < NDIR; d++)
        #pragma unroll
        for (int t = 0; t < 4; t++) acc[d][t] = 0.f;

    RowP<S, D0, ND, NDIR, 0>::run(sp, acc);

    int b = img / 3, c = img % 3;
    size_t outoff = (size_t)(y0 + ty) * W + x0 + xg * 4;
    float* obase = dout + (size_t)(b*87 + c*29 + CH0) * HW + outoff;
    #pragma unroll
    for (int d = 0; d < NDIR; d++) {
        float* op = obase + (size_t)d * HW;
        *(float4*)op = make_float4(acc[d][0], acc[d][1], acc[d][2], acc[d][3]);
    }
}

// ---------------- launch ----------------
extern "C" void kernel_launch(void* const* d_in, const int* in_sizes, int n_in,
                              void* d_out, int out_size) {
    const float* x = (const float*)d_in[0];
    float* out = (float*)d_out;

    dim3 grid(W / 64, H / 16, NIMG);   // 6 x 24 x 24
    lp_fused_kernel<<<grid, 256>>>(x, out);

    // scale 0: 4 dirs -> channels 0..3
    dir_conv_kernel<0, 0, 4, 4, 0><<<grid, 256>>>(out);
    // scale 1: 8 dirs -> channels 4..11
    dir_conv_kernel<1, 0, 8, 8, 4><<<grid, 256>>>(out);
    // scale 2: 16 dirs in two 8-dir groups -> channels 12..27
    dir_conv_kernel<2, 0, 16, 8, 12><<<grid, 256>>>(out);
    dir_conv_kernel<2, 8, 16, 8, 20><<<grid, 256>>>(out);
}

// round 10
// speedup vs baseline: 4.1761x; 1.1068x over previous
#include <cuda_runtime.h>
#include <math.h>

#define W 384
#define H 384
#define HW (W*H)
#define NIMG 24

#define TAU 2e-5f

// ---------------- scratch (no allocations allowed) ----------------
__device__ float g_bp[3][NIMG*HW];        // bandpasses

// =====================================================================
// Compile-time double-precision math (matches numpy float64 to ~1e-15)
// =====================================================================
constexpr double PI_ = 3.14159265358979323846264338327950288;

constexpr double cexp(double x) {
    const double LN2 = 0.69314718055994530941723212145817657;
    int n = (int)(x / LN2 + (x >= 0 ? 0.5 : -0.5));
    double r = x - (double)n * LN2;
    double t = 1.0, term = 1.0;
    for (int i = 1; i <= 22; i++) { term *= r / (double)i; t += term; }
    double s = 1.0;
    if (n >= 0) for (int i = 0; i < n; i++)  s *= 2.0;
    else        for (int i = 0; i < -n; i++) s *= 0.5;
    return t * s;
}
constexpr double ccos(double x) {
    double t = x; bool neg = false;
    if (t > PI_ * 0.5) { t = PI_ - t; neg = true; }
    double t2 = t*t, term = 1.0, s = 1.0;
    for (int i = 1; i <= 16; i++) { term *= -t2 / (double)((2*i-1)*(2*i)); s += term; }
    return neg ? -s : s;
}
constexpr double csin(double x) {
    double t = x;
    if (t > PI_ * 0.5) t = PI_ - t;
    double t2 = t*t, term = t, s = t;
    for (int i = 1; i <= 16; i++) { term *= -t2 / (double)((2*i)*(2*i+1)); s += term; }
    return s;
}
constexpr double csqrt(double x) {
    if (x <= 0.0) return 0.0;
    double y = (x > 1.0) ? x : 1.0;
    for (int i = 0; i < 80; i++) y = 0.5 * (y + x / y);
    return y;
}

// ---------------- oriented 15x15 filters, computed at compile time ----------------
struct F225 { float w[225]; };

constexpr F225 make_filt(int s, int d, int nd) {
    double scale = (double)(s + 1);
    double sx = 2.0 * scale, sy = 0.5 * scale;
    double ang = PI_ * (double)d / (double)nd;
    double ca = ccos(ang), sa = csin(ang);
    double k[225] = {};
    double sum = 0.0;
    for (int i = 0; i < 15; i++) {
        for (int j = 0; j < 15; j++) {
            double X = (double)(j - 7), Y = (double)(i - 7);
            double Xr = X * ca - Y * sa;
            double Yr = X * sa + Y * ca;
            double v = cexp(-0.5 * (Xr*Xr/(sx*sx) + Yr*Yr/(sy*sy))) * Xr / (sx*sx);
            k[i*15 + j] = v;
            sum += v;
        }
    }
    double mean = sum / 225.0;
    double nr = 0.0;
    for (int i = 0; i < 225; i++) { k[i] -= mean; nr += k[i]*k[i]; }
    nr = csqrt(nr);
    double inv = (nr > 1e-6) ? 1.0 / nr : 1.0;
    F225 f{};
    for (int i = 0; i < 225; i++) f.w[i] = (float)(k[i] * inv);
    return f;
}

template<int S, int D, int ND>
struct Filt { static constexpr F225 f = make_filt(S, D, ND); };
template<int S, int D, int ND> constexpr F225 Filt<S, D, ND>::f;

// ---------------- 5x5 gaussian lowpass at compile time ----------------
struct F25 { float w[25]; };
constexpr F25 make_lp() {
    double g[5] = {}; double s1 = 0.0;
    for (int i = 0; i < 5; i++) { double a = (double)(i - 2); g[i] = cexp(-0.5*a*a); s1 += g[i]; }
    double k1[5] = {};
    for (int i = 0; i < 5; i++) k1[i] = g[i] / s1;
    double k2[25] = {}; double s2 = 0.0;
    for (int i = 0; i < 5; i++)
        for (int j = 0; j < 5; j++) { k2[i*5+j] = k1[i]*k1[j]; s2 += k2[i*5+j]; }
    F25 f{};
    for (int i = 0; i < 25; i++) f.w[i] = (float)(k2[i] / s2);
    return f;
}
struct LPF { static constexpr F25 f = make_lp(); };
constexpr F25 LPF::f;

__device__ __forceinline__ int reflect_idx(int i, int n) {
    if (i < 0) return -i;
    if (i >= n) return 2*n - 2 - i;
    return i;
}

// =====================================================================
// Fused 3-stage Laplacian pyramid (unchanged from R9, passing)
// =====================================================================
#define B0S 76
#define B1S 72
#define B2S 68

template<int SSTR, int I, int J>
struct C5 {
    static __device__ __forceinline__ void run(const float* src, float& a) {
        constexpr float w = LPF::f.w[I*5 + J];
        a = fmaf(src[I*SSTR + J], w, a);
        C5<SSTR, I, J+1>::run(src, a);
    }
};
template<int SSTR, int I> struct C5<SSTR, I, 5> {
    static __device__ __forceinline__ void run(const float* src, float& a) {
        C5<SSTR, I+1, 0>::run(src, a);
    }
};
template<int SSTR> struct C5<SSTR, 5, 0> {
    static __device__ __forceinline__ void run(const float*, float&) {}
};
template<int SSTR>
__device__ __forceinline__ float conv5(const float* src) {
    float a = 0.f;
    C5<SSTR, 0, 0>::run(src, a);
    return a;
}

__global__ __launch_bounds__(256) void lp_fused_kernel(const float* __restrict__ xin,
                                                       float* __restrict__ dout) {
    __shared__ float b0[28 * B0S];
    __shared__ float b1[24 * B1S];
    __shared__ float b2[20 * B2S];

    int img = blockIdx.z;
    int x0 = blockIdx.x * 64;
    int y0 = blockIdx.y * 16;
    const float* base = xin + (size_t)img * HW;
    int tid = threadIdx.x;

    for (int i = tid; i < 28 * B0S; i += 256) {
        int r = i / B0S, c = i - r * B0S;
        int gy = reflect_idx(y0 - 6 + r, H);
        int gx = reflect_idx(x0 - 6 + c, W);
        b0[i] = __ldg(base + gy * W + gx);
    }
    __syncthreads();

    for (int i = tid; i < 24 * B1S; i += 256) {
        int r = i / B1S, c = i - r * B1S;
        b1[i] = conv5<B0S>(&b0[r * B0S + c]);
    }
    __syncthreads();

    size_t pbase = (size_t)img * HW;
    {
        int i = tid;
        int ty = i >> 4, tx4 = (i & 15) * 4;
        float v[4];
        #pragma unroll
        for (int t = 0; t < 4; t++)
            v[t] = b0[(ty+6)*B0S + tx4 + t + 6] - b1[(ty+4)*B1S + tx4 + t + 4];
        *(float4*)&g_bp[0][pbase + (size_t)(y0+ty)*W + x0 + tx4] =
            make_float4(v[0], v[1], v[2], v[3]);
    }
    for (int i = tid; i < 20 * B2S; i += 256) {
        int r = i / B2S, c = i - r * B2S;
        b2[i] = conv5<B1S>(&b1[r * B1S + c]);
    }
    __syncthreads();

    int b = img / 3, cc = img % 3;
    float* lpo = dout + (size_t)(b*87 + cc*29 + 28) * HW;
    for (int i = tid; i < 1024; i += 256) {
        int ty = i >> 6, tx = i & 63;
        size_t pix = (size_t)(y0+ty)*W + x0 + tx;
        size_t go = pbase + pix;
        float l1 = b1[(ty+4)*B1S + tx + 4];
        float l2 = b2[(ty+2)*B2S + tx + 2];
        g_bp[1][go] = l1 - l2;
        float l3 = conv5<B2S>(&b2[ty * B2S + tx]);
        g_bp[2][go] = l2 - l3;
        lpo[pix] = l3;
    }
}

// =====================================================================
// Directional 15x15 conv — NDIR dirs/block, antisymmetry + zero-skip.
// Tile 64x16, 256 threads, 4 px/thread.
// =====================================================================
#define DT_W 64
#define DT_H 16
#define DROWS 30
#define DCOLS 78
#define DSTR  84       // 84%32=20 -> 8 consecutive rows hit distinct banks

template<int S, int D0, int ND, int NDIR, int I, int DD = 0>
struct AnySig {
    static constexpr float w = Filt<S, D0+DD, ND>::f.w[I];
    static constexpr bool v = (w > TAU || w < -TAU) || AnySig<S, D0, ND, NDIR, I, DD+1>::v;
};
template<int S, int D0, int ND, int NDIR, int I>
struct AnySig<S, D0, ND, NDIR, I, NDIR> { static constexpr bool v = false; };

template<int S, int D0, int ND, int NDIR, int I, int DD = 0>
struct FmaN {
    static __device__ __forceinline__ void run(const float (&d)[4], float (&acc)[NDIR][4]) {
        constexpr float w = Filt<S, D0+DD, ND>::f.w[I];
        if constexpr (w > TAU || w < -TAU) {
            #pragma unroll
            for (int t = 0; t < 4; t++)
                acc[DD][t] = fmaf(d[t], w, acc[DD][t]);
        }
        FmaN<S, D0, ND, NDIR, I, DD+1>::run(d, acc);
    }
};
template<int S, int D0, int ND, int NDIR, int I>
struct FmaN<S, D0, ND, NDIR, I, NDIR> {
    static __device__ __forceinline__ void run(const float (&)[4], float (&)[NDIR][4]) {}
};

template<int S, int D0, int ND, int NDIR, int KY, int KX>
struct KxP {
    static __device__ __forceinline__ void run(const float (&rA)[20], const float (&rB)[20],
                                               float (&acc)[NDIR][4]) {
        if constexpr (AnySig<S, D0, ND, NDIR, KY*15 + KX>::v) {
            float d[4];
            #pragma unroll
            for (int t = 0; t < 4; t++)
                d[t] = rA[KX + t] - rB[14 - KX + t];
            FmaN<S, D0, ND, NDIR, KY*15 + KX>::run(d, acc);
        }
        KxP<S, D0, ND, NDIR, KY, KX+1>::run(rA, rB, acc);
    }
};
template<int S, int D0, int ND, int NDIR, int KY>
struct KxP<S, D0, ND, NDIR, KY, 15> {
    static __device__ __forceinline__ void run(const float (&)[20], const float (&)[20],
                                               float (&)[NDIR][4]) {}
};

template<int S, int D0, int ND, int NDIR, int KX>
struct KxC {
    static __device__ __forceinline__ void run(const float (&r)[20], float (&acc)[NDIR][4]) {
        if constexpr (AnySig<S, D0, ND, NDIR, 7*15 + KX>::v) {
            float d[4];
            #pragma unroll
            for (int t = 0; t < 4; t++)
                d[t] = r[KX + t] - r[14 - KX + t];
            FmaN<S, D0, ND, NDIR, 7*15 + KX>::run(d, acc);
        }
        KxC<S, D0, ND, NDIR, KX+1>::run(r, acc);
    }
};
template<int S, int D0, int ND, int NDIR>
struct KxC<S, D0, ND, NDIR, 7> {
    static __device__ __forceinline__ void run(const float (&)[20], float (&)[NDIR][4]) {}
};

template<int S, int D0, int ND, int NDIR, int KY>
struct RowP {
    static __device__ __forceinline__ void run(const float* sp, float (&acc)[NDIR][4]) {
        float rA[20], rB[20];
        const float4* pa = (const float4*)(sp + KY * DSTR);
        const float4* pb = (const float4*)(sp + (14 - KY) * DSTR);
        #pragma unroll
        for (int q = 0; q < 5; q++) {
            float4 a = pa[q];
            rA[4*q] = a.x; rA[4*q+1] = a.y; rA[4*q+2] = a.z; rA[4*q+3] = a.w;
            float4 b = pb[q];
            rB[4*q] = b.x; rB[4*q+1] = b.y; rB[4*q+2] = b.z; rB[4*q+3] = b.w;
        }
        KxP<S, D0, ND, NDIR, KY, 0>::run(rA, rB, acc);
        RowP<S, D0, ND, NDIR, KY+1>::run(sp, acc);
    }
};
template<int S, int D0, int ND, int NDIR>
struct RowP<S, D0, ND, NDIR, 7> {
    static __device__ __forceinline__ void run(const float* sp, float (&acc)[NDIR][4]) {
        float r[20];
        const float4* pa = (const float4*)(sp + 7 * DSTR);
        #pragma unroll
        for (int q = 0; q < 5; q++) {
            float4 a = pa[q];
            r[4*q] = a.x; r[4*q+1] = a.y; r[4*q+2] = a.z; r[4*q+3] = a.w;
        }
        KxC<S, D0, ND, NDIR, 0>::run(r, acc);
    }
};

template<int S, int D0, int ND, int NDIR, int CH0>
__global__ __launch_bounds__(256) void dir_conv_kernel(float* __restrict__ dout) {
    __shared__ float s_in[DROWS * DSTR];

    int img = blockIdx.z;
    int x0 = blockIdx.x * DT_W;
    int y0 = blockIdx.y * DT_H;
    const float* bp = g_bp[S] + (size_t)img * HW;
    int tid = threadIdx.x;

    for (int i = tid; i < DROWS * DCOLS; i += 256) {
        int r = i / DCOLS, c = i - r * DCOLS;
        int gy = reflect_idx(y0 + r - 7, H);
        int gx = reflect_idx(x0 + c - 7, W);
        s_in[r * DSTR + c] = __ldg(bp + gy * W + gx);
    }
    __syncthreads();

    int sub = tid & 7;
    int xg  = (tid >> 3) & 15;
    int rg  = tid >> 7;
    int ty  = rg * 8 + sub;
    const float* sp = &s_in[ty * DSTR + xg * 4];

    float acc[NDIR][4];
    #pragma unroll
    for (int d = 0; d < NDIR; d++)
        #pragma unroll
        for (int t = 0; t < 4; t++) acc[d][t] = 0.f;

    RowP<S, D0, ND, NDIR, 0>::run(sp, acc);

    int b = img / 3, c = img % 3;
    size_t outoff = (size_t)(y0 + ty) * W + x0 + xg * 4;
    float* obase = dout + (size_t)(b*87 + c*29 + CH0) * HW + outoff;
    #pragma unroll
    for (int d = 0; d < NDIR; d++) {
        float* op = obase + (size_t)d * HW;
        *(float4*)op = make_float4(acc[d][0], acc[d][1], acc[d][2], acc[d][3]);
    }
}

// ---------------- launch ----------------
extern "C" void kernel_launch(void* const* d_in, const int* in_sizes, int n_in,
                              void* d_out, int out_size) {
    const float* x = (const float*)d_in[0];
    float* out = (float*)d_out;

    dim3 grid(W / 64, H / 16, NIMG);   // 6 x 24 x 24
    lp_fused_kernel<<<grid, 256>>>(x, out);

    // scale 0: 4 dirs -> channels 0..3
    dir_conv_kernel<0, 0, 4, 4, 0><<<grid, 256>>>(out);
    // scale 1: 8 dirs -> channels 4..11
    dir_conv_kernel<1, 0, 8, 8, 4><<<grid, 256>>>(out);
    // scale 2: all 16 dirs in ONE block -> channels 12..27
    dir_conv_kernel<2, 0, 16, 16, 12><<<grid, 256>>>(out);
}

// round 11
// speedup vs baseline: 4.7301x; 1.1327x over previous
#include <cuda_runtime.h>
#include <math.h>

#define W 384
#define H 384
#define HW (W*H)
#define NIMG 24

#define TAU 1e-4f

// ---------------- scratch (no allocations allowed) ----------------
__device__ float g_bp[3][NIMG*HW];        // bandpasses

// =====================================================================
// Compile-time double-precision math (matches numpy float64 to ~1e-15)
// =====================================================================
constexpr double PI_ = 3.14159265358979323846264338327950288;

constexpr double cexp(double x) {
    const double LN2 = 0.69314718055994530941723212145817657;
    int n = (int)(x / LN2 + (x >= 0 ? 0.5 : -0.5));
    double r = x - (double)n * LN2;
    double t = 1.0, term = 1.0;
    for (int i = 1; i <= 22; i++) { term *= r / (double)i; t += term; }
    double s = 1.0;
    if (n >= 0) for (int i = 0; i < n; i++)  s *= 2.0;
    else        for (int i = 0; i < -n; i++) s *= 0.5;
    return t * s;
}
constexpr double ccos(double x) {
    double t = x; bool neg = false;
    if (t > PI_ * 0.5) { t = PI_ - t; neg = true; }
    double t2 = t*t, term = 1.0, s = 1.0;
    for (int i = 1; i <= 16; i++) { term *= -t2 / (double)((2*i-1)*(2*i)); s += term; }
    return neg ? -s : s;
}
constexpr double csin(double x) {
    double t = x;
    if (t > PI_ * 0.5) t = PI_ - t;
    double t2 = t*t, term = t, s = t;
    for (int i = 1; i <= 16; i++) { term *= -t2 / (double)((2*i)*(2*i+1)); s += term; }
    return s;
}
constexpr double csqrt(double x) {
    if (x <= 0.0) return 0.0;
    double y = (x > 1.0) ? x : 1.0;
    for (int i = 0; i < 80; i++) y = 0.5 * (y + x / y);
    return y;
}

// ---------------- oriented 15x15 filters, computed at compile time ----------------
struct F225 { float w[225]; };

constexpr F225 make_filt(int s, int d, int nd) {
    double scale = (double)(s + 1);
    double sx = 2.0 * scale, sy = 0.5 * scale;
    double ang = PI_ * (double)d / (double)nd;
    double ca = ccos(ang), sa = csin(ang);
    double k[225] = {};
    double sum = 0.0;
    for (int i = 0; i < 15; i++) {
        for (int j = 0; j < 15; j++) {
            double X = (double)(j - 7), Y = (double)(i - 7);
            double Xr = X * ca - Y * sa;
            double Yr = X * sa + Y * ca;
            double v = cexp(-0.5 * (Xr*Xr/(sx*sx) + Yr*Yr/(sy*sy))) * Xr / (sx*sx);
            k[i*15 + j] = v;
            sum += v;
        }
    }
    double mean = sum / 225.0;
    double nr = 0.0;
    for (int i = 0; i < 225; i++) { k[i] -= mean; nr += k[i]*k[i]; }
    nr = csqrt(nr);
    double inv = (nr > 1e-6) ? 1.0 / nr : 1.0;
    F225 f{};
    for (int i = 0; i < 225; i++) f.w[i] = (float)(k[i] * inv);
    return f;
}

template<int S, int D, int ND>
struct Filt { static constexpr F225 f = make_filt(S, D, ND); };
template<int S, int D, int ND> constexpr F225 Filt<S, D, ND>::f;

// ---------------- 5x5 gaussian lowpass at compile time ----------------
struct F25 { float w[25]; };
constexpr F25 make_lp() {
    double g[5] = {}; double s1 = 0.0;
    for (int i = 0; i < 5; i++) { double a = (double)(i - 2); g[i] = cexp(-0.5*a*a); s1 += g[i]; }
    double k1[5] = {};
    for (int i = 0; i < 5; i++) k1[i] = g[i] / s1;
    double k2[25] = {}; double s2 = 0.0;
    for (int i = 0; i < 5; i++)
        for (int j = 0; j < 5; j++) { k2[i*5+j] = k1[i]*k1[j]; s2 += k2[i*5+j]; }
    F25 f{};
    for (int i = 0; i < 25; i++) f.w[i] = (float)(k2[i] / s2);
    return f;
}
struct LPF { static constexpr F25 f = make_lp(); };
constexpr F25 LPF::f;

__device__ __forceinline__ int reflect_idx(int i, int n) {
    if (i < 0) return -i;
    if (i >= n) return 2*n - 2 - i;
    return i;
}

// =====================================================================
// Fused 3-stage Laplacian pyramid (unchanged — passing since R9)
// =====================================================================
#define B0S 76
#define B1S 72
#define B2S 68

template<int SSTR, int I, int J>
struct C5 {
    static __device__ __forceinline__ void run(const float* src, float& a) {
        constexpr float w = LPF::f.w[I*5 + J];
        a = fmaf(src[I*SSTR + J], w, a);
        C5<SSTR, I, J+1>::run(src, a);
    }
};
template<int SSTR, int I> struct C5<SSTR, I, 5> {
    static __device__ __forceinline__ void run(const float* src, float& a) {
        C5<SSTR, I+1, 0>::run(src, a);
    }
};
template<int SSTR> struct C5<SSTR, 5, 0> {
    static __device__ __forceinline__ void run(const float*, float&) {}
};
template<int SSTR>
__device__ __forceinline__ float conv5(const float* src) {
    float a = 0.f;
    C5<SSTR, 0, 0>::run(src, a);
    return a;
}

__global__ __launch_bounds__(256) void lp_fused_kernel(const float* __restrict__ xin,
                                                       float* __restrict__ dout) {
    __shared__ float b0[28 * B0S];
    __shared__ float b1[24 * B1S];
    __shared__ float b2[20 * B2S];

    int img = blockIdx.z;
    int x0 = blockIdx.x * 64;
    int y0 = blockIdx.y * 16;
    const float* base = xin + (size_t)img * HW;
    int tid = threadIdx.x;

    for (int i = tid; i < 28 * B0S; i += 256) {
        int r = i / B0S, c = i - r * B0S;
        int gy = reflect_idx(y0 - 6 + r, H);
        int gx = reflect_idx(x0 - 6 + c, W);
        b0[i] = __ldg(base + gy * W + gx);
    }
    __syncthreads();

    for (int i = tid; i < 24 * B1S; i += 256) {
        int r = i / B1S, c = i - r * B1S;
        b1[i] = conv5<B0S>(&b0[r * B0S + c]);
    }
    __syncthreads();

    size_t pbase = (size_t)img * HW;
    {
        int i = tid;
        int ty = i >> 4, tx4 = (i & 15) * 4;
        float v[4];
        #pragma unroll
        for (int t = 0; t < 4; t++)
            v[t] = b0[(ty+6)*B0S + tx4 + t + 6] - b1[(ty+4)*B1S + tx4 + t + 4];
        *(float4*)&g_bp[0][pbase + (size_t)(y0+ty)*W + x0 + tx4] =
            make_float4(v[0], v[1], v[2], v[3]);
    }
    for (int i = tid; i < 20 * B2S; i += 256) {
        int r = i / B2S, c = i - r * B2S;
        b2[i] = conv5<B1S>(&b1[r * B1S + c]);
    }
    __syncthreads();

    int b = img / 3, cc = img % 3;
    float* lpo = dout + (size_t)(b*87 + cc*29 + 28) * HW;
    for (int i = tid; i < 1024; i += 256) {
        int ty = i >> 6, tx = i & 63;
        size_t pix = (size_t)(y0+ty)*W + x0 + tx;
        size_t go = pbase + pix;
        float l1 = b1[(ty+4)*B1S + tx + 4];
        float l2 = b2[(ty+2)*B2S + tx + 2];
        g_bp[1][go] = l1 - l2;
        float l3 = conv5<B2S>(&b2[ty * B2S + tx]);
        g_bp[2][go] = l2 - l3;
        lpo[pix] = l3;
    }
}

// =====================================================================
// Directional 15x15 conv — NDIR dirs/block, NPX px/thread,
// antisymmetry + zero-skip. Tile 64 x TILE_H, 256 threads.
// =====================================================================
#define DT_W 64
#define DCOLS 78
#define DSTR  84       // 84%32=20 -> 8 consecutive rows hit distinct banks

template<int S, int D0, int ND, int NDIR, int I, int DD = 0>
struct AnySig {
    static constexpr float w = Filt<S, D0+DD, ND>::f.w[I];
    static constexpr bool v = (w > TAU || w < -TAU) || AnySig<S, D0, ND, NDIR, I, DD+1>::v;
};
template<int S, int D0, int ND, int NDIR, int I>
struct AnySig<S, D0, ND, NDIR, I, NDIR> { static constexpr bool v = false; };

template<int S, int D0, int ND, int NDIR, int NPX, int I, int DD = 0>
struct FmaN {
    static __device__ __forceinline__ void run(const float (&d)[NPX], float (&acc)[NDIR][NPX]) {
        constexpr float w = Filt<S, D0+DD, ND>::f.w[I];
        if constexpr (w > TAU || w < -TAU) {
            #pragma unroll
            for (int t = 0; t < NPX; t++)
                acc[DD][t] = fmaf(d[t], w, acc[DD][t]);
        }
        FmaN<S, D0, ND, NDIR, NPX, I, DD+1>::run(d, acc);
    }
};
template<int S, int D0, int ND, int NDIR, int NPX, int I>
struct FmaN<S, D0, ND, NDIR, NPX, I, NDIR> {
    static __device__ __forceinline__ void run(const float (&)[NPX], float (&)[NDIR][NPX]) {}
};

// row buffer length: NPX=4 -> 20 (5x float4); NPX=2 -> 16 (8x float2)
template<int NPX> struct RowLen { static constexpr int v = (NPX == 4) ? 20 : 16; };

template<int NPX>
__device__ __forceinline__ void load_row(const float* p, float (&r)[RowLen<NPX>::v]) {
    if constexpr (NPX == 4) {
        const float4* rp = (const float4*)p;
        #pragma unroll
        for (int q = 0; q < 5; q++) {
            float4 v = rp[q];
            r[4*q] = v.x; r[4*q+1] = v.y; r[4*q+2] = v.z; r[4*q+3] = v.w;
        }
    } else {
        const float2* rp = (const float2*)p;
        #pragma unroll
        for (int q = 0; q < 8; q++) {
            float2 v = rp[q];
            r[2*q] = v.x; r[2*q+1] = v.y;
        }
    }
}

template<int S, int D0, int ND, int NDIR, int NPX, int KY, int KX>
struct KxP {
    static __device__ __forceinline__ void run(const float (&rA)[RowLen<NPX>::v],
                                               const float (&rB)[RowLen<NPX>::v],
                                               float (&acc)[NDIR][NPX]) {
        if constexpr (AnySig<S, D0, ND, NDIR, KY*15 + KX>::v) {
            float d[NPX];
            #pragma unroll
            for (int t = 0; t < NPX; t++)
                d[t] = rA[KX + t] - rB[14 - KX + t];
            FmaN<S, D0, ND, NDIR, NPX, KY*15 + KX>::run(d, acc);
        }
        KxP<S, D0, ND, NDIR, NPX, KY, KX+1>::run(rA, rB, acc);
    }
};
template<int S, int D0, int ND, int NDIR, int NPX, int KY>
struct KxP<S, D0, ND, NDIR, NPX, KY, 15> {
    static __device__ __forceinline__ void run(const float (&)[RowLen<NPX>::v],
                                               const float (&)[RowLen<NPX>::v],
                                               float (&)[NDIR][NPX]) {}
};

template<int S, int D0, int ND, int NDIR, int NPX, int KX>
struct KxC {
    static __device__ __forceinline__ void run(const float (&r)[RowLen<NPX>::v],
                                               float (&acc)[NDIR][NPX]) {
        if constexpr (AnySig<S, D0, ND, NDIR, 7*15 + KX>::v) {
            float d[NPX];
            #pragma unroll
            for (int t = 0; t < NPX; t++)
                d[t] = r[KX + t] - r[14 - KX + t];
            FmaN<S, D0, ND, NDIR, NPX, 7*15 + KX>::run(d, acc);
        }
        KxC<S, D0, ND, NDIR, NPX, KX+1>::run(r, acc);
    }
};
template<int S, int D0, int ND, int NDIR, int NPX>
struct KxC<S, D0, ND, NDIR, NPX, 7> {
    static __device__ __forceinline__ void run(const float (&)[RowLen<NPX>::v],
                                               float (&)[NDIR][NPX]) {}
};

template<int S, int D0, int ND, int NDIR, int NPX, int KY>
struct RowP {
    static __device__ __forceinline__ void run(const float* sp, float (&acc)[NDIR][NPX]) {
        float rA[RowLen<NPX>::v], rB[RowLen<NPX>::v];
        load_row<NPX>(sp + KY * DSTR, rA);
        load_row<NPX>(sp + (14 - KY) * DSTR, rB);
        KxP<S, D0, ND, NDIR, NPX, KY, 0>::run(rA, rB, acc);
        RowP<S, D0, ND, NDIR, NPX, KY+1>::run(sp, acc);
    }
};
template<int S, int D0, int ND, int NDIR, int NPX>
struct RowP<S, D0, ND, NDIR, NPX, 7> {
    static __device__ __forceinline__ void run(const float* sp, float (&acc)[NDIR][NPX]) {
        float r[RowLen<NPX>::v];
        load_row<NPX>(sp + 7 * DSTR, r);
        KxC<S, D0, ND, NDIR, NPX, 0>::run(r, acc);
    }
};

template<int S, int D0, int ND, int NDIR, int CH0, int NPX, int TILE_H>
__global__ __launch_bounds__(256) void dir_conv_kernel(float* __restrict__ dout) {
    constexpr int DROWS = TILE_H + 14;
    __shared__ float s_in[DROWS * DSTR];

    int img = blockIdx.z;
    int x0 = blockIdx.x * DT_W;
    int y0 = blockIdx.y * TILE_H;
    const float* bp = g_bp[S] + (size_t)img * HW;
    int tid = threadIdx.x;

    for (int i = tid; i < DROWS * DCOLS; i += 256) {
        int r = i / DCOLS, c = i - r * DCOLS;
        int gy = reflect_idx(y0 + r - 7, H);
        int gx = reflect_idx(x0 + c - 7, W);
        s_in[r * DSTR + c] = __ldg(bp + gy * W + gx);
    }
    __syncthreads();

    // 8 consecutive lanes = 8 consecutive rows (conflict-free)
    int sub = tid & 7;
    int ty, xg;
    if constexpr (NPX == 4) {
        xg = (tid >> 3) & 15;          // 16 x-groups of 4 px
        ty = (tid >> 7) * 8 + sub;     // 0..15
    } else {
        xg = tid >> 3;                 // 32 x-groups of 2 px
        ty = sub;                      // 0..7
    }
    const float* sp = &s_in[ty * DSTR + xg * NPX];

    float acc[NDIR][NPX];
    #pragma unroll
    for (int d = 0; d < NDIR; d++)
        #pragma unroll
        for (int t = 0; t < NPX; t++) acc[d][t] = 0.f;

    RowP<S, D0, ND, NDIR, NPX, 0>::run(sp, acc);

    int b = img / 3, c = img % 3;
    size_t outoff = (size_t)(y0 + ty) * W + x0 + xg * NPX;
    float* obase = dout + (size_t)(b*87 + c*29 + CH0) * HW + outoff;
    #pragma unroll
    for (int d = 0; d < NDIR; d++) {
        float* op = obase + (size_t)d * HW;
        if constexpr (NPX == 4)
            *(float4*)op = make_float4(acc[d][0], acc[d][1], acc[d][2], acc[d][3]);
        else
            *(float2*)op = make_float2(acc[d][0], acc[d][1]);
    }
}

// ---------------- launch ----------------
extern "C" void kernel_launch(void* const* d_in, const int* in_sizes, int n_in,
                              void* d_out, int out_size) {
    const float* x = (const float*)d_in[0];
    float* out = (float*)d_out;

    dim3 grid16(W / 64, H / 16, NIMG);   // 6 x 24 x 24
    dim3 grid8 (W / 64, H / 8,  NIMG);   // 6 x 48 x 24

    lp_fused_kernel<<<grid16, 256>>>(x, out);

    // scale 0: 4 dirs, 4 px/thread -> channels 0..3
    dir_conv_kernel<0, 0, 4, 4, 0, 4, 16><<<grid16, 256>>>(out);
    // scale 1: 8 dirs, 4 px/thread -> channels 4..11
    dir_conv_kernel<1, 0, 8, 8, 4, 4, 16><<<grid16, 256>>>(out);
    // scale 2: 16 dirs, 2 px/thread (low regs -> 3 blocks/SM) -> channels 12..27
    dir_conv_kernel<2, 0, 16, 16, 12, 2, 8><<<grid8, 256>>>(out);
}

// round 12
// speedup vs baseline: 4.8055x; 1.0159x over previous
#include <cuda_runtime.h>
#include <math.h>

#define W 384
#define H 384
#define HW (W*H)
#define NIMG 24

#define TAU 1e-4f

// ---------------- scratch (no allocations allowed) ----------------
__device__ float g_bp[3][NIMG*HW];        // bandpasses

// =====================================================================
// Compile-time double-precision math (matches numpy float64 to ~1e-15)
// =====================================================================
constexpr double PI_ = 3.14159265358979323846264338327950288;

constexpr double cexp(double x) {
    const double LN2 = 0.69314718055994530941723212145817657;
    int n = (int)(x / LN2 + (x >= 0 ? 0.5 : -0.5));
    double r = x - (double)n * LN2;
    double t = 1.0, term = 1.0;
    for (int i = 1; i <= 22; i++) { term *= r / (double)i; t += term; }
    double s = 1.0;
    if (n >= 0) for (int i = 0; i < n; i++)  s *= 2.0;
    else        for (int i = 0; i < -n; i++) s *= 0.5;
    return t * s;
}
constexpr double ccos(double x) {
    double t = x; bool neg = false;
    if (t > PI_ * 0.5) { t = PI_ - t; neg = true; }
    double t2 = t*t, term = 1.0, s = 1.0;
    for (int i = 1; i <= 16; i++) { term *= -t2 / (double)((2*i-1)*(2*i)); s += term; }
    return neg ? -s : s;
}
constexpr double csin(double x) {
    double t = x;
    if (t > PI_ * 0.5) t = PI_ - t;
    double t2 = t*t, term = t, s = t;
    for (int i = 1; i <= 16; i++) { term *= -t2 / (double)((2*i)*(2*i+1)); s += term; }
    return s;
}
constexpr double csqrt(double x) {
    if (x <= 0.0) return 0.0;
    double y = (x > 1.0) ? x : 1.0;
    for (int i = 0; i < 80; i++) y = 0.5 * (y + x / y);
    return y;
}

// ---------------- oriented 15x15 filters, computed at compile time ----------------
struct F225 { float w[225]; };

constexpr F225 make_filt(int s, int d, int nd) {
    double scale = (double)(s + 1);
    double sx = 2.0 * scale, sy = 0.5 * scale;
    double ang = PI_ * (double)d / (double)nd;
    double ca = ccos(ang), sa = csin(ang);
    double k[225] = {};
    double sum = 0.0;
    for (int i = 0; i < 15; i++) {
        for (int j = 0; j < 15; j++) {
            double X = (double)(j - 7), Y = (double)(i - 7);
            double Xr = X * ca - Y * sa;
            double Yr = X * sa + Y * ca;
            double v = cexp(-0.5 * (Xr*Xr/(sx*sx) + Yr*Yr/(sy*sy))) * Xr / (sx*sx);
            k[i*15 + j] = v;
            sum += v;
        }
    }
    double mean = sum / 225.0;
    double nr = 0.0;
    for (int i = 0; i < 225; i++) { k[i] -= mean; nr += k[i]*k[i]; }
    nr = csqrt(nr);
    double inv = (nr > 1e-6) ? 1.0 / nr : 1.0;
    F225 f{};
    for (int i = 0; i < 225; i++) f.w[i] = (float)(k[i] * inv);
    return f;
}

template<int S, int D, int ND>
struct Filt { static constexpr F225 f = make_filt(S, D, ND); };
template<int S, int D, int ND> constexpr F225 Filt<S, D, ND>::f;

// ---------------- 5x5 gaussian lowpass at compile time ----------------
struct F25 { float w[25]; };
constexpr F25 make_lp() {
    double g[5] = {}; double s1 = 0.0;
    for (int i = 0; i < 5; i++) { double a = (double)(i - 2); g[i] = cexp(-0.5*a*a); s1 += g[i]; }
    double k1[5] = {};
    for (int i = 0; i < 5; i++) k1[i] = g[i] / s1;
    double k2[25] = {}; double s2 = 0.0;
    for (int i = 0; i < 5; i++)
        for (int j = 0; j < 5; j++) { k2[i*5+j] = k1[i]*k1[j]; s2 += k2[i*5+j]; }
    F25 f{};
    for (int i = 0; i < 25; i++) f.w[i] = (float)(k2[i] / s2);
    return f;
}
struct LPF { static constexpr F25 f = make_lp(); };
constexpr F25 LPF::f;

__device__ __forceinline__ int reflect_idx(int i, int n) {
    if (i < 0) return -i;
    if (i >= n) return 2*n - 2 - i;
    return i;
}

// subtraction as FFMA-imm (rt=1 vs FADD rt=2); bit-identical to a-b
__device__ __forceinline__ float fsub_fma(float a, float b) {
    return fmaf(b, -1.0f, a);
}

// =====================================================================
// Fused 3-stage Laplacian pyramid (passing since R9)
// =====================================================================
#define B0S 76
#define B1S 72
#define B2S 68

template<int SSTR, int I, int J>
struct C5 {
    static __device__ __forceinline__ void run(const float* src, float& a) {
        constexpr float w = LPF::f.w[I*5 + J];
        a = fmaf(src[I*SSTR + J], w, a);
        C5<SSTR, I, J+1>::run(src, a);
    }
};
template<int SSTR, int I> struct C5<SSTR, I, 5> {
    static __device__ __forceinline__ void run(const float* src, float& a) {
        C5<SSTR, I+1, 0>::run(src, a);
    }
};
template<int SSTR> struct C5<SSTR, 5, 0> {
    static __device__ __forceinline__ void run(const float*, float&) {}
};
template<int SSTR>
__device__ __forceinline__ float conv5(const float* src) {
    float a = 0.f;
    C5<SSTR, 0, 0>::run(src, a);
    return a;
}

__global__ __launch_bounds__(256) void lp_fused_kernel(const float* __restrict__ xin,
                                                       float* __restrict__ dout) {
    __shared__ float b0[28 * B0S];
    __shared__ float b1[24 * B1S];
    __shared__ float b2[20 * B2S];

    int img = blockIdx.z;
    int x0 = blockIdx.x * 64;
    int y0 = blockIdx.y * 16;
    const float* base = xin + (size_t)img * HW;
    int tid = threadIdx.x;

    for (int i = tid; i < 28 * B0S; i += 256) {
        int r = i / B0S, c = i - r * B0S;
        int gy = reflect_idx(y0 - 6 + r, H);
        int gx = reflect_idx(x0 - 6 + c, W);
        b0[i] = __ldg(base + gy * W + gx);
    }
    __syncthreads();

    for (int i = tid; i < 24 * B1S; i += 256) {
        int r = i / B1S, c = i - r * B1S;
        b1[i] = conv5<B0S>(&b0[r * B0S + c]);
    }
    __syncthreads();

    size_t pbase = (size_t)img * HW;
    {
        int i = tid;
        int ty = i >> 4, tx4 = (i & 15) * 4;
        float v[4];
        #pragma unroll
        for (int t = 0; t < 4; t++)
            v[t] = b0[(ty+6)*B0S + tx4 + t + 6] - b1[(ty+4)*B1S + tx4 + t + 4];
        *(float4*)&g_bp[0][pbase + (size_t)(y0+ty)*W + x0 + tx4] =
            make_float4(v[0], v[1], v[2], v[3]);
    }
    for (int i = tid; i < 20 * B2S; i += 256) {
        int r = i / B2S, c = i - r * B2S;
        b2[i] = conv5<B1S>(&b1[r * B1S + c]);
    }
    __syncthreads();

    int b = img / 3, cc = img % 3;
    float* lpo = dout + (size_t)(b*87 + cc*29 + 28) * HW;
    for (int i = tid; i < 1024; i += 256) {
        int ty = i >> 6, tx = i & 63;
        size_t pix = (size_t)(y0+ty)*W + x0 + tx;
        size_t go = pbase + pix;
        float l1 = b1[(ty+4)*B1S + tx + 4];
        float l2 = b2[(ty+2)*B2S + tx + 2];
        g_bp[1][go] = l1 - l2;
        float l3 = conv5<B2S>(&b2[ty * B2S + tx]);
        g_bp[2][go] = l2 - l3;
        lpo[pix] = l3;
    }
}

// =====================================================================
// Directional 15x15 conv — NDIR dirs/block, NPX px/thread, NT threads,
// antisymmetry + zero-skip + FFMA-imm diffs. Tile 64 x TILE_H.
// =====================================================================
#define DT_W 64
#define DCOLS 78
#define DSTR  84       // 84%32=20 -> 8 consecutive rows hit distinct banks

template<int S, int D0, int ND, int NDIR, int I, int DD = 0>
struct AnySig {
    static constexpr float w = Filt<S, D0+DD, ND>::f.w[I];
    static constexpr bool v = (w > TAU || w < -TAU) || AnySig<S, D0, ND, NDIR, I, DD+1>::v;
};
template<int S, int D0, int ND, int NDIR, int I>
struct AnySig<S, D0, ND, NDIR, I, NDIR> { static constexpr bool v = false; };

template<int S, int D0, int ND, int NDIR, int NPX, int I, int DD = 0>
struct FmaN {
    static __device__ __forceinline__ void run(const float (&d)[NPX], float (&acc)[NDIR][NPX]) {
        constexpr float w = Filt<S, D0+DD, ND>::f.w[I];
        if constexpr (w > TAU || w < -TAU) {
            #pragma unroll
            for (int t = 0; t < NPX; t++)
                acc[DD][t] = fmaf(d[t], w, acc[DD][t]);
        }
        FmaN<S, D0, ND, NDIR, NPX, I, DD+1>::run(d, acc);
    }
};
template<int S, int D0, int ND, int NDIR, int NPX, int I>
struct FmaN<S, D0, ND, NDIR, NPX, I, NDIR> {
    static __device__ __forceinline__ void run(const float (&)[NPX], float (&)[NDIR][NPX]) {}
};

template<int NPX> struct RowLen { static constexpr int v = (NPX == 4) ? 20 : 16; };

template<int NPX>
__device__ __forceinline__ void load_row(const float* p, float (&r)[RowLen<NPX>::v]) {
    if constexpr (NPX == 4) {
        const float4* rp = (const float4*)p;
        #pragma unroll
        for (int q = 0; q < 5; q++) {
            float4 v = rp[q];
            r[4*q] = v.x; r[4*q+1] = v.y; r[4*q+2] = v.z; r[4*q+3] = v.w;
        }
    } else {
        const float2* rp = (const float2*)p;
        #pragma unroll
        for (int q = 0; q < 8; q++) {
            float2 v = rp[q];
            r[2*q] = v.x; r[2*q+1] = v.y;
        }
    }
}

template<int S, int D0, int ND, int NDIR, int NPX, int KY, int KX>
struct KxP {
    static __device__ __forceinline__ void run(const float (&rA)[RowLen<NPX>::v],
                                               const float (&rB)[RowLen<NPX>::v],
                                               float (&acc)[NDIR][NPX]) {
        if constexpr (AnySig<S, D0, ND, NDIR, KY*15 + KX>::v) {
            float d[NPX];
            #pragma unroll
            for (int t = 0; t < NPX; t++)
                d[t] = fsub_fma(rA[KX + t], rB[14 - KX + t]);
            FmaN<S, D0, ND, NDIR, NPX, KY*15 + KX>::run(d, acc);
        }
        KxP<S, D0, ND, NDIR, NPX, KY, KX+1>::run(rA, rB, acc);
    }
};
template<int S, int D0, int ND, int NDIR, int NPX, int KY>
struct KxP<S, D0, ND, NDIR, NPX, KY, 15> {
    static __device__ __forceinline__ void run(const float (&)[RowLen<NPX>::v],
                                               const float (&)[RowLen<NPX>::v],
                                               float (&)[NDIR][NPX]) {}
};

template<int S, int D0, int ND, int NDIR, int NPX, int KX>
struct KxC {
    static __device__ __forceinline__ void run(const float (&r)[RowLen<NPX>::v],
                                               float (&acc)[NDIR][NPX]) {
        if constexpr (AnySig<S, D0, ND, NDIR, 7*15 + KX>::v) {
            float d[NPX];
            #pragma unroll
            for (int t = 0; t < NPX; t++)
                d[t] = fsub_fma(r[KX + t], r[14 - KX + t]);
            FmaN<S, D0, ND, NDIR, NPX, 7*15 + KX>::run(d, acc);
        }
        KxC<S, D0, ND, NDIR, NPX, KX+1>::run(r, acc);
    }
};
template<int S, int D0, int ND, int NDIR, int NPX>
struct KxC<S, D0, ND, NDIR, NPX, 7> {
    static __device__ __forceinline__ void run(const float (&)[RowLen<NPX>::v],
                                               float (&)[NDIR][NPX]) {}
};

template<int S, int D0, int ND, int NDIR, int NPX, int KY>
struct RowP {
    static __device__ __forceinline__ void run(const float* sp, float (&acc)[NDIR][NPX]) {
        float rA[RowLen<NPX>::v], rB[RowLen<NPX>::v];
        load_row<NPX>(sp + KY * DSTR, rA);
        load_row<NPX>(sp + (14 - KY) * DSTR, rB);
        KxP<S, D0, ND, NDIR, NPX, KY, 0>::run(rA, rB, acc);
        RowP<S, D0, ND, NDIR, NPX, KY+1>::run(sp, acc);
    }
};
template<int S, int D0, int ND, int NDIR, int NPX>
struct RowP<S, D0, ND, NDIR, NPX, 7> {
    static __device__ __forceinline__ void run(const float* sp, float (&acc)[NDIR][NPX]) {
        float r[RowLen<NPX>::v];
        load_row<NPX>(sp + 7 * DSTR, r);
        KxC<S, D0, ND, NDIR, NPX, 0>::run(r, acc);
    }
};

template<int S, int D0, int ND, int NDIR, int CH0, int NPX, int TILE_H, int NT>
__global__ __launch_bounds__(NT) void dir_conv_kernel(float* __restrict__ dout) {
    constexpr int DROWS = TILE_H + 14;
    __shared__ float s_in[DROWS * DSTR];

    int img = blockIdx.z;
    int x0 = blockIdx.x * DT_W;
    int y0 = blockIdx.y * TILE_H;
    const float* bp = g_bp[S] + (size_t)img * HW;
    int tid = threadIdx.x;

    for (int i = tid; i < DROWS * DCOLS; i += NT) {
        int r = i / DCOLS, c = i - r * DCOLS;
        int gy = reflect_idx(y0 + r - 7, H);
        int gx = reflect_idx(x0 + c - 7, W);
        s_in[r * DSTR + c] = __ldg(bp + gy * W + gx);
    }
    __syncthreads();

    // 8 consecutive lanes = 8 consecutive rows (conflict-free)
    int sub = tid & 7;
    int ty, xg;
    if constexpr (NPX == 4) {
        xg = (tid >> 3) & 15;          // 16 x-groups of 4 px
        ty = (tid >> 7) * 8 + sub;     // covers TILE_H=16 with NT=256
    } else {
        xg = (tid >> 3) & 31;          // 32 x-groups of 2 px
        ty = (tid >> 8) * 8 + sub;     // NT=512 -> ty 0..15; NT=256 -> 0..7
    }
    const float* sp = &s_in[ty * DSTR + xg * NPX];

    float acc[NDIR][NPX];
    #pragma unroll
    for (int d = 0; d < NDIR; d++)
        #pragma unroll
        for (int t = 0; t < NPX; t++) acc[d][t] = 0.f;

    RowP<S, D0, ND, NDIR, NPX, 0>::run(sp, acc);

    int b = img / 3, c = img % 3;
    size_t outoff = (size_t)(y0 + ty) * W + x0 + xg * NPX;
    float* obase = dout + (size_t)(b*87 + c*29 + CH0) * HW + outoff;
    #pragma unroll
    for (int d = 0; d < NDIR; d++) {
        float* op = obase + (size_t)d * HW;
        if constexpr (NPX == 4)
            *(float4*)op = make_float4(acc[d][0], acc[d][1], acc[d][2], acc[d][3]);
        else
            *(float2*)op = make_float2(acc[d][0], acc[d][1]);
    }
}

// ---------------- launch ----------------
extern "C" void kernel_launch(void* const* d_in, const int* in_sizes, int n_in,
                              void* d_out, int out_size) {
    const float* x = (const float*)d_in[0];
    float* out = (float*)d_out;

    dim3 grid16(W / 64, H / 16, NIMG);   // 6 x 24 x 24

    lp_fused_kernel<<<grid16, 256>>>(x, out);

    // scale 0: 4 dirs, 4 px/thread, 256 thr -> channels 0..3
    dir_conv_kernel<0, 0, 4, 4, 0, 4, 16, 256><<<grid16, 256>>>(out);
    // scale 1: 8 dirs, 4 px/thread, 256 thr -> channels 4..11
    dir_conv_kernel<1, 0, 8, 8, 4, 4, 16, 256><<<grid16, 256>>>(out);
    // scale 2: 16 dirs, 2 px/thread, 512 thr, tile 64x16 -> channels 12..27
    dir_conv_kernel<2, 0, 16, 16, 12, 2, 16, 512><<<grid16, 512>>>(out);
}

// round 14
// speedup vs baseline: 5.1597x; 1.0737x over previous
#include <cuda_runtime.h>
#include <math.h>

#define W 384
#define H 384
#define HW (W*H)
#define NIMG 24

#define TAU 1.5e-4f

// ---------------- scratch (no allocations allowed) ----------------
__device__ float g_bp[3][NIMG*HW];        // bandpasses

// =====================================================================
// Compile-time double-precision math (matches numpy float64 to ~1e-15)
// =====================================================================
constexpr double PI_ = 3.14159265358979323846264338327950288;

constexpr double cexp(double x) {
    const double LN2 = 0.69314718055994530941723212145817657;
    int n = (int)(x / LN2 + (x >= 0 ? 0.5 : -0.5));
    double r = x - (double)n * LN2;
    double t = 1.0, term = 1.0;
    for (int i = 1; i <= 22; i++) { term *= r / (double)i; t += term; }
    double s = 1.0;
    if (n >= 0) for (int i = 0; i < n; i++)  s *= 2.0;
    else        for (int i = 0; i < -n; i++) s *= 0.5;
    return t * s;
}
constexpr double ccos(double x) {
    double t = x; bool neg = false;
    if (t > PI_ * 0.5) { t = PI_ - t; neg = true; }
    double t2 = t*t, term = 1.0, s = 1.0;
    for (int i = 1; i <= 16; i++) { term *= -t2 / (double)((2*i-1)*(2*i)); s += term; }
    return neg ? -s : s;
}
constexpr double csin(double x) {
    double t = x;
    if (t > PI_ * 0.5) t = PI_ - t;
    double t2 = t*t, term = t, s = t;
    for (int i = 1; i <= 16; i++) { term *= -t2 / (double)((2*i)*(2*i+1)); s += term; }
    return s;
}
constexpr double csqrt(double x) {
    if (x <= 0.0) return 0.0;
    double y = (x > 1.0) ? x : 1.0;
    for (int i = 0; i < 80; i++) y = 0.5 * (y + x / y);
    return y;
}

// ---------------- oriented 15x15 filters, computed at compile time ----------------
struct F225 { float w[225]; };

constexpr F225 make_filt(int s, int d, int nd) {
    double scale = (double)(s + 1);
    double sx = 2.0 * scale, sy = 0.5 * scale;
    double ang = PI_ * (double)d / (double)nd;
    double ca = ccos(ang), sa = csin(ang);
    double k[225] = {};
    double sum = 0.0;
    for (int i = 0; i < 15; i++) {
        for (int j = 0; j < 15; j++) {
            double X = (double)(j - 7), Y = (double)(i - 7);
            double Xr = X * ca - Y * sa;
            double Yr = X * sa + Y * ca;
            double v = cexp(-0.5 * (Xr*Xr/(sx*sx) + Yr*Yr/(sy*sy))) * Xr / (sx*sx);
            k[i*15 + j] = v;
            sum += v;
        }
    }
    double mean = sum / 225.0;
    double nr = 0.0;
    for (int i = 0; i < 225; i++) { k[i] -= mean; nr += k[i]*k[i]; }
    nr = csqrt(nr);
    double inv = (nr > 1e-6) ? 1.0 / nr : 1.0;
    F225 f{};
    for (int i = 0; i < 225; i++) f.w[i] = (float)(k[i] * inv);
    return f;
}

template<int S, int D, int ND>
struct Filt { static constexpr F225 f = make_filt(S, D, ND); };
template<int S, int D, int ND> constexpr F225 Filt<S, D, ND>::f;

// ---------------- separable 5-tap gaussian at compile time ----------------
// k2 = outer(k1,k1)/sum(outer) ; horiz uses k1, vert uses k1/s2
// template so the constexpr member is device-foldable (same as Filt)
struct F5 { float h[5]; float v[5]; };
constexpr F5 make_k1() {
    double g[5] = {}; double s1 = 0.0;
    for (int i = 0; i < 5; i++) { double a = (double)(i - 2); g[i] = cexp(-0.5*a*a); s1 += g[i]; }
    double k1[5] = {};
    for (int i = 0; i < 5; i++) k1[i] = g[i] / s1;
    double s2 = 0.0;
    for (int i = 0; i < 5; i++)
        for (int j = 0; j < 5; j++) s2 += k1[i]*k1[j];
    F5 f{};
    for (int i = 0; i < 5; i++) { f.h[i] = (float)k1[i]; f.v[i] = (float)(k1[i] / s2); }
    return f;
}
template<int DUMMY>
struct K1T { static constexpr F5 f = make_k1(); };
template<int DUMMY> constexpr F5 K1T<DUMMY>::f;

__device__ __forceinline__ int reflect_idx(int i, int n) {
    if (i < 0) return -i;
    if (i >= n) return 2*n - 2 - i;
    return i;
}

// subtraction as FFMA-imm (rt=1 vs FADD rt=2); bit-identical to a-b
__device__ __forceinline__ float fsub_fma(float a, float b) {
    return fmaf(b, -1.0f, a);
}

// 5-tap horiz / vert with immediate weights (template recursion -> folded)
template<int I>
struct H5t {
    static __device__ __forceinline__ void run(const float* s, float& a) {
        constexpr float w = K1T<0>::f.h[I];
        a = fmaf(s[I], w, a);
        H5t<I+1>::run(s, a);
    }
};
template<> struct H5t<5> { static __device__ __forceinline__ void run(const float*, float&) {} };
__device__ __forceinline__ float h5(const float* s) { float a = 0.f; H5t<0>::run(s, a); return a; }

template<int STR, int I>
struct V5t {
    static __device__ __forceinline__ void run(const float* s, float& a) {
        constexpr float w = K1T<0>::f.v[I];
        a = fmaf(s[I*STR], w, a);
        V5t<STR, I+1>::run(s, a);
    }
};
template<int STR> struct V5t<STR, 5> { static __device__ __forceinline__ void run(const float*, float&) {} };
template<int STR>
__device__ __forceinline__ float v5(const float* s) { float a = 0.f; V5t<STR,0>::run(s, a); return a; }

// =====================================================================
// Fused 3-stage Laplacian pyramid, separable 5-tap passes.
// Tile 64x16 output, halo 6.
// =====================================================================
#define B0S 76

__global__ __launch_bounds__(256) void lp_fused_kernel(const float* __restrict__ xin,
                                                       float* __restrict__ dout) {
    __shared__ float b0[28 * B0S];   // input  28 x 76
    __shared__ float t1[28 * 72];    // horiz1 28 x 72
    __shared__ float b1[24 * 72];    // lp1    24 x 72
    __shared__ float t2[24 * 68];    // horiz2 24 x 68
    __shared__ float b2[20 * 68];    // lp2    20 x 68
    __shared__ float t3[20 * 64];    // horiz3 20 x 64

    int img = blockIdx.z;
    int x0 = blockIdx.x * 64;
    int y0 = blockIdx.y * 16;
    const float* base = xin + (size_t)img * HW;
    int tid = threadIdx.x;

    for (int i = tid; i < 28 * B0S; i += 256) {
        int r = i / B0S, c = i - r * B0S;
        int gy = reflect_idx(y0 - 6 + r, H);
        int gx = reflect_idx(x0 - 6 + c, W);
        b0[i] = __ldg(base + gy * W + gx);
    }
    __syncthreads();

    // stage 1 horiz: 28 x 72
    for (int i = tid; i < 28 * 72; i += 256) {
        int r = i / 72, c = i - r * 72;
        t1[i] = h5(&b0[r * B0S + c]);
    }
    __syncthreads();
    // stage 1 vert: 24 x 72
    for (int i = tid; i < 24 * 72; i += 256) {
        int r = i / 72, c = i - r * 72;
        b1[i] = v5<72>(&t1[r * 72 + c]);
    }
    __syncthreads();

    size_t pbase = (size_t)img * HW;
    // bp0 (center)
    {
        int i = tid;
        int ty = i >> 4, tx4 = (i & 15) * 4;
        float v[4];
        #pragma unroll
        for (int t = 0; t < 4; t++)
            v[t] = b0[(ty+6)*B0S + tx4 + t + 6] - b1[(ty+4)*72 + tx4 + t + 4];
        *(float4*)&g_bp[0][pbase + (size_t)(y0+ty)*W + x0 + tx4] =
            make_float4(v[0], v[1], v[2], v[3]);
    }
    // stage 2 horiz: 24 x 68
    for (int i = tid; i < 24 * 68; i += 256) {
        int r = i / 68, c = i - r * 68;
        t2[i] = h5(&b1[r * 72 + c]);
    }
    __syncthreads();
    // stage 2 vert: 20 x 68
    for (int i = tid; i < 20 * 68; i += 256) {
        int r = i / 68, c = i - r * 68;
        b2[i] = v5<68>(&t2[r * 68 + c]);
    }
    __syncthreads();
    // stage 3 horiz: 20 x 64
    for (int i = tid; i < 20 * 64; i += 256) {
        int r = i / 64, c = i - r * 64;
        t3[i] = h5(&b2[r * 68 + c]);
    }
    __syncthreads();

    // bp1 + bp2 + lowpass (center only); stage 3 vert inline
    int b = img / 3, cc = img % 3;
    float* lpo = dout + (size_t)(b*87 + cc*29 + 28) * HW;
    for (int i = tid; i < 1024; i += 256) {
        int ty = i >> 6, tx = i & 63;
        size_t pix = (size_t)(y0+ty)*W + x0 + tx;
        size_t go = pbase + pix;
        float l1 = b1[(ty+4)*72 + tx + 4];
        float l2 = b2[(ty+2)*68 + tx + 2];
        g_bp[1][go] = l1 - l2;
        float l3 = v5<64>(&t3[ty * 64 + tx]);
        g_bp[2][go] = l2 - l3;
        lpo[pix] = l3;
    }
}

// =====================================================================
// Directional 15x15 conv — NDIR dirs/block, NPX px/thread, NT threads,
// NPASS row-passes per tile. Antisymmetry + zero-skip + FFMA-imm diffs.
// =====================================================================
#define DT_W 64
#define DCOLS 78
#define DSTR  84       // 84%32=20 -> 8 consecutive rows hit distinct banks

template<int S, int D0, int ND, int NDIR, int I, int DD = 0>
struct AnySig {
    static constexpr float w = Filt<S, D0+DD, ND>::f.w[I];
    static constexpr bool v = (w > TAU || w < -TAU) || AnySig<S, D0, ND, NDIR, I, DD+1>::v;
};
template<int S, int D0, int ND, int NDIR, int I>
struct AnySig<S, D0, ND, NDIR, I, NDIR> { static constexpr bool v = false; };

template<int S, int D0, int ND, int NDIR, int NPX, int I, int DD = 0>
struct FmaN {
    static __device__ __forceinline__ void run(const float (&d)[NPX], float (&acc)[NDIR][NPX]) {
        constexpr float w = Filt<S, D0+DD, ND>::f.w[I];
        if constexpr (w > TAU || w < -TAU) {
            #pragma unroll
            for (int t = 0; t < NPX; t++)
                acc[DD][t] = fmaf(d[t], w, acc[DD][t]);
        }
        FmaN<S, D0, ND, NDIR, NPX, I, DD+1>::run(d, acc);
    }
};
template<int S, int D0, int ND, int NDIR, int NPX, int I>
struct FmaN<S, D0, ND, NDIR, NPX, I, NDIR> {
    static __device__ __forceinline__ void run(const float (&)[NPX], float (&)[NDIR][NPX]) {}
};

template<int NPX> struct RowLen { static constexpr int v = (NPX == 4) ? 20 : 16; };

template<int NPX>
__device__ __forceinline__ void load_row(const float* p, float (&r)[RowLen<NPX>::v]) {
    if constexpr (NPX == 4) {
        const float4* rp = (const float4*)p;
        #pragma unroll
        for (int q = 0; q < 5; q++) {
            float4 v = rp[q];
            r[4*q] = v.x; r[4*q+1] = v.y; r[4*q+2] = v.z; r[4*q+3] = v.w;
        }
    } else {
        const float2* rp = (const float2*)p;
        #pragma unroll
        for (int q = 0; q < 8; q++) {
            float2 v = rp[q];
            r[2*q] = v.x; r[2*q+1] = v.y;
        }
    }
}

template<int S, int D0, int ND, int NDIR, int NPX, int KY, int KX>
struct KxP {
    static __device__ __forceinline__ void run(const float (&rA)[RowLen<NPX>::v],
                                               const float (&rB)[RowLen<NPX>::v],
                                               float (&acc)[NDIR][NPX]) {
        if constexpr (AnySig<S, D0, ND, NDIR, KY*15 + KX>::v) {
            float d[NPX];
            #pragma unroll
            for (int t = 0; t < NPX; t++)
                d[t] = fsub_fma(rA[KX + t], rB[14 - KX + t]);
            FmaN<S, D0, ND, NDIR, NPX, KY*15 + KX>::run(d, acc);
        }
        KxP<S, D0, ND, NDIR, NPX, KY, KX+1>::run(rA, rB, acc);
    }
};
template<int S, int D0, int ND, int NDIR, int NPX, int KY>
struct KxP<S, D0, ND, NDIR, NPX, KY, 15> {
    static __device__ __forceinline__ void run(const float (&)[RowLen<NPX>::v],
                                               const float (&)[RowLen<NPX>::v],
                                               float (&)[NDIR][NPX]) {}
};

template<int S, int D0, int ND, int NDIR, int NPX, int KX>
struct KxC {
    static __device__ __forceinline__ void run(const float (&r)[RowLen<NPX>::v],
                                               float (&acc)[NDIR][NPX]) {
        if constexpr (AnySig<S, D0, ND, NDIR, 7*15 + KX>::v) {
            float d[NPX];
            #pragma unroll
            for (int t = 0; t < NPX; t++)
                d[t] = fsub_fma(r[KX + t], r[14 - KX + t]);
            FmaN<S, D0, ND, NDIR, NPX, 7*15 + KX>::run(d, acc);
        }
        KxC<S, D0, ND, NDIR, NPX, KX+1>::run(r, acc);
    }
};
template<int S, int D0, int ND, int NDIR, int NPX>
struct KxC<S, D0, ND, NDIR, NPX, 7> {
    static __device__ __forceinline__ void run(const float (&)[RowLen<NPX>::v],
                                               float (&)[NDIR][NPX]) {}
};

template<int S, int D0, int ND, int NDIR, int NPX, int KY>
struct RowP {
    static __device__ __forceinline__ void run(const float* sp, float (&acc)[NDIR][NPX]) {
        float rA[RowLen<NPX>::v], rB[RowLen<NPX>::v];
        load_row<NPX>(sp + KY * DSTR, rA);
        load_row<NPX>(sp + (14 - KY) * DSTR, rB);
        KxP<S, D0, ND, NDIR, NPX, KY, 0>::run(rA, rB, acc);
        RowP<S, D0, ND, NDIR, NPX, KY+1>::run(sp, acc);
    }
};
template<int S, int D0, int ND, int NDIR, int NPX>
struct RowP<S, D0, ND, NDIR, NPX, 7> {
    static __device__ __forceinline__ void run(const float* sp, float (&acc)[NDIR][NPX]) {
        float r[RowLen<NPX>::v];
        load_row<NPX>(sp + 7 * DSTR, r);
        KxC<S, D0, ND, NDIR, NPX, 0>::run(r, acc);
    }
};

template<int S, int D0, int ND, int NDIR, int CH0, int NPX, int TILE_H, int NT, int NPASS>
__global__ __launch_bounds__(NT) void dir_conv_kernel(float* __restrict__ dout) {
    constexpr int DROWS = TILE_H + 14;
    constexpr int PASS_H = TILE_H / NPASS;
    __shared__ float s_in[DROWS * DSTR];

    int img = blockIdx.z;
    int x0 = blockIdx.x * DT_W;
    int y0 = blockIdx.y * TILE_H;
    const float* bp = g_bp[S] + (size_t)img * HW;
    int tid = threadIdx.x;

    for (int i = tid; i < DROWS * DCOLS; i += NT) {
        int r = i / DCOLS, c = i - r * DCOLS;
        int gy = reflect_idx(y0 + r - 7, H);
        int gx = reflect_idx(x0 + c - 7, W);
        s_in[r * DSTR + c] = __ldg(bp + gy * W + gx);
    }
    __syncthreads();

    // 8 consecutive lanes = 8 consecutive rows (conflict-free)
    int sub = tid & 7;
    int ty0, xg;
    if constexpr (NPX == 4) {
        xg = (tid >> 3) & 15;          // 16 x-groups of 4 px
        ty0 = (tid >> 7) * 8 + sub;
    } else {
        xg = (tid >> 3) & 31;          // 32 x-groups of 2 px
        ty0 = (tid >> 8) * 8 + sub;
    }

    int b = img / 3, c = img % 3;

    #pragma unroll 1
    for (int p = 0; p < NPASS; p++) {
        int ty = ty0 + p * PASS_H;
        const float* sp = &s_in[ty * DSTR + xg * NPX];

        float acc[NDIR][NPX];
        #pragma unroll
        for (int d = 0; d < NDIR; d++)
            #pragma unroll
            for (int t = 0; t < NPX; t++) acc[d][t] = 0.f;

        RowP<S, D0, ND, NDIR, NPX, 0>::run(sp, acc);

        size_t outoff = (size_t)(y0 + ty) * W + x0 + xg * NPX;
        float* obase = dout + (size_t)(b*87 + c*29 + CH0) * HW + outoff;
        #pragma unroll
        for (int d = 0; d < NDIR; d++) {
            float* op = obase + (size_t)d * HW;
            if constexpr (NPX == 4)
                *(float4*)op = make_float4(acc[d][0], acc[d][1], acc[d][2], acc[d][3]);
            else
                *(float2*)op = make_float2(acc[d][0], acc[d][1]);
        }
    }
}

// ---------------- launch ----------------
extern "C" void kernel_launch(void* const* d_in, const int* in_sizes, int n_in,
                              void* d_out, int out_size) {
    const float* x = (const float*)d_in[0];
    float* out = (float*)d_out;

    dim3 grid16(W / 64, H / 16, NIMG);   // 6 x 24 x 24
    dim3 grid32(W / 64, H / 32, NIMG);   // 6 x 12 x 24

    lp_fused_kernel<<<grid16, 256>>>(x, out);

    // scale 0: 4 dirs, 4 px/thread, 256 thr -> channels 0..3
    dir_conv_kernel<0, 0, 4, 4, 0, 4, 16, 256, 1><<<grid16, 256>>>(out);
    // scale 1: 8 dirs, 4 px/thread, 256 thr -> channels 4..11
    dir_conv_kernel<1, 0, 8, 8, 4, 4, 16, 256, 1><<<grid16, 256>>>(out);
    // scale 2: 16 dirs, 2 px/thread, 512 thr, tile 64x32, two passes
    dir_conv_kernel<2, 0, 16, 16, 12, 2, 32, 512, 2><<<grid32, 512>>>(out);
}

// round 15
// speedup vs baseline: 5.1835x; 1.0046x over previous
#include <cuda_runtime.h>
#include <math.h>

#define W 384
#define H 384
#define HW (W*H)
#define NIMG 24

#define TAU 2e-4f

// ---------------- scratch (no allocations allowed) ----------------
__device__ float g_bp[3][NIMG*HW];        // bandpasses

// =====================================================================
// Compile-time double-precision math (matches numpy float64 to ~1e-15)
// =====================================================================
constexpr double PI_ = 3.14159265358979323846264338327950288;

constexpr double cexp(double x) {
    const double LN2 = 0.69314718055994530941723212145817657;
    int n = (int)(x / LN2 + (x >= 0 ? 0.5 : -0.5));
    double r = x - (double)n * LN2;
    double t = 1.0, term = 1.0;
    for (int i = 1; i <= 22; i++) { term *= r / (double)i; t += term; }
    double s = 1.0;
    if (n >= 0) for (int i = 0; i < n; i++)  s *= 2.0;
    else        for (int i = 0; i < -n; i++) s *= 0.5;
    return t * s;
}
constexpr double ccos(double x) {
    double t = x; bool neg = false;
    if (t > PI_ * 0.5) { t = PI_ - t; neg = true; }
    double t2 = t*t, term = 1.0, s = 1.0;
    for (int i = 1; i <= 16; i++) { term *= -t2 / (double)((2*i-1)*(2*i)); s += term; }
    return neg ? -s : s;
}
constexpr double csin(double x) {
    double t = x;
    if (t > PI_ * 0.5) t = PI_ - t;
    double t2 = t*t, term = t, s = t;
    for (int i = 1; i <= 16; i++) { term *= -t2 / (double)((2*i)*(2*i+1)); s += term; }
    return s;
}
constexpr double csqrt(double x) {
    if (x <= 0.0) return 0.0;
    double y = (x > 1.0) ? x : 1.0;
    for (int i = 0; i < 80; i++) y = 0.5 * (y + x / y);
    return y;
}

// ---------------- oriented 15x15 filters, computed at compile time ----------------
struct F225 { float w[225]; };

constexpr F225 make_filt(int s, int d, int nd) {
    double scale = (double)(s + 1);
    double sx = 2.0 * scale, sy = 0.5 * scale;
    double ang = PI_ * (double)d / (double)nd;
    double ca = ccos(ang), sa = csin(ang);
    double k[225] = {};
    double sum = 0.0;
    for (int i = 0; i < 15; i++) {
        for (int j = 0; j < 15; j++) {
            double X = (double)(j - 7), Y = (double)(i - 7);
            double Xr = X * ca - Y * sa;
            double Yr = X * sa + Y * ca;
            double v = cexp(-0.5 * (Xr*Xr/(sx*sx) + Yr*Yr/(sy*sy))) * Xr / (sx*sx);
            k[i*15 + j] = v;
            sum += v;
        }
    }
    double mean = sum / 225.0;
    double nr = 0.0;
    for (int i = 0; i < 225; i++) { k[i] -= mean; nr += k[i]*k[i]; }
    nr = csqrt(nr);
    double inv = (nr > 1e-6) ? 1.0 / nr : 1.0;
    F225 f{};
    for (int i = 0; i < 225; i++) f.w[i] = (float)(k[i] * inv);
    return f;
}

template<int S, int D, int ND>
struct Filt { static constexpr F225 f = make_filt(S, D, ND); };
template<int S, int D, int ND> constexpr F225 Filt<S, D, ND>::f;

// ---------------- separable 5-tap gaussian at compile time ----------------
struct F5 { float h[5]; float v[5]; };
constexpr F5 make_k1() {
    double g[5] = {}; double s1 = 0.0;
    for (int i = 0; i < 5; i++) { double a = (double)(i - 2); g[i] = cexp(-0.5*a*a); s1 += g[i]; }
    double k1[5] = {};
    for (int i = 0; i < 5; i++) k1[i] = g[i] / s1;
    double s2 = 0.0;
    for (int i = 0; i < 5; i++)
        for (int j = 0; j < 5; j++) s2 += k1[i]*k1[j];
    F5 f{};
    for (int i = 0; i < 5; i++) { f.h[i] = (float)k1[i]; f.v[i] = (float)(k1[i] / s2); }
    return f;
}
template<int DUMMY>
struct K1T { static constexpr F5 f = make_k1(); };
template<int DUMMY> constexpr F5 K1T<DUMMY>::f;

__device__ __forceinline__ int reflect_idx(int i, int n) {
    if (i < 0) return -i;
    if (i >= n) return 2*n - 2 - i;
    return i;
}

// subtraction as FFMA-imm (rt=1 vs FADD rt=2); bit-identical to a-b
__device__ __forceinline__ float fsub_fma(float a, float b) {
    return fmaf(b, -1.0f, a);
}

// 5-tap horiz / vert with immediate weights
template<int I>
struct H5t {
    static __device__ __forceinline__ void run(const float* s, float& a) {
        constexpr float w = K1T<0>::f.h[I];
        a = fmaf(s[I], w, a);
        H5t<I+1>::run(s, a);
    }
};
template<> struct H5t<5> { static __device__ __forceinline__ void run(const float*, float&) {} };
__device__ __forceinline__ float h5(const float* s) { float a = 0.f; H5t<0>::run(s, a); return a; }

template<int STR, int I>
struct V5t {
    static __device__ __forceinline__ void run(const float* s, float& a) {
        constexpr float w = K1T<0>::f.v[I];
        a = fmaf(s[I*STR], w, a);
        V5t<STR, I+1>::run(s, a);
    }
};
template<int STR> struct V5t<STR, 5> { static __device__ __forceinline__ void run(const float*, float&) {} };
template<int STR>
__device__ __forceinline__ float v5(const float* s) { float a = 0.f; V5t<STR,0>::run(s, a); return a; }

// =====================================================================
// Fused 3-stage Laplacian pyramid, separable 5-tap passes.
// Tile 64x16 output, halo 6.
// =====================================================================
#define B0S 76

__global__ __launch_bounds__(256) void lp_fused_kernel(const float* __restrict__ xin,
                                                       float* __restrict__ dout) {
    __shared__ float b0[28 * B0S];   // input  28 x 76
    __shared__ float t1[28 * 72];    // horiz1 28 x 72
    __shared__ float b1[24 * 72];    // lp1    24 x 72
    __shared__ float t2[24 * 68];    // horiz2 24 x 68
    __shared__ float b2[20 * 68];    // lp2    20 x 68
    __shared__ float t3[20 * 64];    // horiz3 20 x 64

    int img = blockIdx.z;
    int x0 = blockIdx.x * 64;
    int y0 = blockIdx.y * 16;
    const float* base = xin + (size_t)img * HW;
    int tid = threadIdx.x;

    for (int i = tid; i < 28 * B0S; i += 256) {
        int r = i / B0S, c = i - r * B0S;
        int gy = reflect_idx(y0 - 6 + r, H);
        int gx = reflect_idx(x0 - 6 + c, W);
        b0[i] = __ldg(base + gy * W + gx);
    }
    __syncthreads();

    for (int i = tid; i < 28 * 72; i += 256) {
        int r = i / 72, c = i - r * 72;
        t1[i] = h5(&b0[r * B0S + c]);
    }
    __syncthreads();
    for (int i = tid; i < 24 * 72; i += 256) {
        int r = i / 72, c = i - r * 72;
        b1[i] = v5<72>(&t1[r * 72 + c]);
    }
    __syncthreads();

    size_t pbase = (size_t)img * HW;
    {
        int i = tid;
        int ty = i >> 4, tx4 = (i & 15) * 4;
        float v[4];
        #pragma unroll
        for (int t = 0; t < 4; t++)
            v[t] = b0[(ty+6)*B0S + tx4 + t + 6] - b1[(ty+4)*72 + tx4 + t + 4];
        *(float4*)&g_bp[0][pbase + (size_t)(y0+ty)*W + x0 + tx4] =
            make_float4(v[0], v[1], v[2], v[3]);
    }
    for (int i = tid; i < 24 * 68; i += 256) {
        int r = i / 68, c = i - r * 68;
        t2[i] = h5(&b1[r * 72 + c]);
    }
    __syncthreads();
    for (int i = tid; i < 20 * 68; i += 256) {
        int r = i / 68, c = i - r * 68;
        b2[i] = v5<68>(&t2[r * 68 + c]);
    }
    __syncthreads();
    for (int i = tid; i < 20 * 64; i += 256) {
        int r = i / 64, c = i - r * 64;
        t3[i] = h5(&b2[r * 68 + c]);
    }
    __syncthreads();

    int b = img / 3, cc = img % 3;
    float* lpo = dout + (size_t)(b*87 + cc*29 + 28) * HW;
    for (int i = tid; i < 1024; i += 256) {
        int ty = i >> 6, tx = i & 63;
        size_t pix = (size_t)(y0+ty)*W + x0 + tx;
        size_t go = pbase + pix;
        float l1 = b1[(ty+4)*72 + tx + 4];
        float l2 = b2[(ty+2)*68 + tx + 2];
        g_bp[1][go] = l1 - l2;
        float l3 = v5<64>(&t3[ty * 64 + tx]);
        g_bp[2][go] = l2 - l3;
        lpo[pix] = l3;
    }
}

// =====================================================================
// Directional 15x15 conv — NDIR dirs/block, NPX px/thread, NT threads,
// NPASS row-passes per tile. Antisymmetry + zero-skip + FFMA-imm diffs.
// =====================================================================
#define DT_W 64
#define DCOLS 78
#define DSTR  84       // 84%32=20 -> 8 consecutive rows hit distinct banks

template<int S, int D0, int ND, int NDIR, int I, int DD = 0>
struct AnySig {
    static constexpr float w = Filt<S, D0+DD, ND>::f.w[I];
    static constexpr bool v = (w > TAU || w < -TAU) || AnySig<S, D0, ND, NDIR, I, DD+1>::v;
};
template<int S, int D0, int ND, int NDIR, int I>
struct AnySig<S, D0, ND, NDIR, I, NDIR> { static constexpr bool v = false; };

template<int S, int D0, int ND, int NDIR, int NPX, int I, int DD = 0>
struct FmaN {
    static __device__ __forceinline__ void run(const float (&d)[NPX], float (&acc)[NDIR][NPX]) {
        constexpr float w = Filt<S, D0+DD, ND>::f.w[I];
        if constexpr (w > TAU || w < -TAU) {
            #pragma unroll
            for (int t = 0; t < NPX; t++)
                acc[DD][t] = fmaf(d[t], w, acc[DD][t]);
        }
        FmaN<S, D0, ND, NDIR, NPX, I, DD+1>::run(d, acc);
    }
};
template<int S, int D0, int ND, int NDIR, int NPX, int I>
struct FmaN<S, D0, ND, NDIR, NPX, I, NDIR> {
    static __device__ __forceinline__ void run(const float (&)[NPX], float (&)[NDIR][NPX]) {}
};

template<int NPX> struct RowLen { static constexpr int v = (NPX == 4) ? 20 : 16; };

template<int NPX>
__device__ __forceinline__ void load_row(const float* p, float (&r)[RowLen<NPX>::v]) {
    if constexpr (NPX == 4) {
        const float4* rp = (const float4*)p;
        #pragma unroll
        for (int q = 0; q < 5; q++) {
            float4 v = rp[q];
            r[4*q] = v.x; r[4*q+1] = v.y; r[4*q+2] = v.z; r[4*q+3] = v.w;
        }
    } else {
        const float2* rp = (const float2*)p;
        #pragma unroll
        for (int q = 0; q < 8; q++) {
            float2 v = rp[q];
            r[2*q] = v.x; r[2*q+1] = v.y;
        }
    }
}

template<int S, int D0, int ND, int NDIR, int NPX, int KY, int KX>
struct KxP {
    static __device__ __forceinline__ void run(const float (&rA)[RowLen<NPX>::v],
                                               const float (&rB)[RowLen<NPX>::v],
                                               float (&acc)[NDIR][NPX]) {
        if constexpr (AnySig<S, D0, ND, NDIR, KY*15 + KX>::v) {
            float d[NPX];
            #pragma unroll
            for (int t = 0; t < NPX; t++)
                d[t] = fsub_fma(rA[KX + t], rB[14 - KX + t]);
            FmaN<S, D0, ND, NDIR, NPX, KY*15 + KX>::run(d, acc);
        }
        KxP<S, D0, ND, NDIR, NPX, KY, KX+1>::run(rA, rB, acc);
    }
};
template<int S, int D0, int ND, int NDIR, int NPX, int KY>
struct KxP<S, D0, ND, NDIR, NPX, KY, 15> {
    static __device__ __forceinline__ void run(const float (&)[RowLen<NPX>::v],
                                               const float (&)[RowLen<NPX>::v],
                                               float (&)[NDIR][NPX]) {}
};

template<int S, int D0, int ND, int NDIR, int NPX, int KX>
struct KxC {
    static __device__ __forceinline__ void run(const float (&r)[RowLen<NPX>::v],
                                               float (&acc)[NDIR][NPX]) {
        if constexpr (AnySig<S, D0, ND, NDIR, 7*15 + KX>::v) {
            float d[NPX];
            #pragma unroll
            for (int t = 0; t < NPX; t++)
                d[t] = fsub_fma(r[KX + t], r[14 - KX + t]);
            FmaN<S, D0, ND, NDIR, NPX, 7*15 + KX>::run(d, acc);
        }
        KxC<S, D0, ND, NDIR, NPX, KX+1>::run(r, acc);
    }
};
template<int S, int D0, int ND, int NDIR, int NPX>
struct KxC<S, D0, ND, NDIR, NPX, 7> {
    static __device__ __forceinline__ void run(const float (&)[RowLen<NPX>::v],
                                               float (&)[NDIR][NPX]) {}
};

template<int S, int D0, int ND, int NDIR, int NPX, int KY>
struct RowP {
    static __device__ __forceinline__ void run(const float* sp, float (&acc)[NDIR][NPX]) {
        float rA[RowLen<NPX>::v], rB[RowLen<NPX>::v];
        load_row<NPX>(sp + KY * DSTR, rA);
        load_row<NPX>(sp + (14 - KY) * DSTR, rB);
        KxP<S, D0, ND, NDIR, NPX, KY, 0>::run(rA, rB, acc);
        RowP<S, D0, ND, NDIR, NPX, KY+1>::run(sp, acc);
    }
};
template<int S, int D0, int ND, int NDIR, int NPX>
struct RowP<S, D0, ND, NDIR, NPX, 7> {
    static __device__ __forceinline__ void run(const float* sp, float (&acc)[NDIR][NPX]) {
        float r[RowLen<NPX>::v];
        load_row<NPX>(sp + 7 * DSTR, r);
        KxC<S, D0, ND, NDIR, NPX, 0>::run(r, acc);
    }
};

template<int S, int D0, int ND, int NDIR, int CH0, int NPX, int TILE_H, int NT, int NPASS>
__global__ __launch_bounds__(NT) void dir_conv_kernel(float* __restrict__ dout) {
    constexpr int DROWS = TILE_H + 14;
    constexpr int PASS_H = TILE_H / NPASS;
    __shared__ float s_in[DROWS * DSTR];

    int img = blockIdx.z;
    int x0 = blockIdx.x * DT_W;
    int y0 = blockIdx.y * TILE_H;
    const float* bp = g_bp[S] + (size_t)img * HW;
    int tid = threadIdx.x;

    for (int i = tid; i < DROWS * DCOLS; i += NT) {
        int r = i / DCOLS, c = i - r * DCOLS;
        int gy = reflect_idx(y0 + r - 7, H);
        int gx = reflect_idx(x0 + c - 7, W);
        s_in[r * DSTR + c] = __ldg(bp + gy * W + gx);
    }
    __syncthreads();

    // 8 consecutive lanes = 8 consecutive rows (conflict-free)
    int sub = tid & 7;
    int ty0, xg;
    if constexpr (NPX == 4) {
        xg = (tid >> 3) & 15;          // 16 x-groups of 4 px
        ty0 = (tid >> 7) * 8 + sub;    // NT=256 -> 0..15 ; NT=512 -> 0..31
    } else {
        xg = (tid >> 3) & 31;          // 32 x-groups of 2 px
        ty0 = (tid >> 8) * 8 + sub;    // NT=512 -> 0..15
    }

    int b = img / 3, c = img % 3;

    #pragma unroll 1
    for (int p = 0; p < NPASS; p++) {
        int ty = ty0 + p * PASS_H;
        const float* sp = &s_in[ty * DSTR + xg * NPX];

        float acc[NDIR][NPX];
        #pragma unroll
        for (int d = 0; d < NDIR; d++)
            #pragma unroll
            for (int t = 0; t < NPX; t++) acc[d][t] = 0.f;

        RowP<S, D0, ND, NDIR, NPX, 0>::run(sp, acc);

        size_t outoff = (size_t)(y0 + ty) * W + x0 + xg * NPX;
        float* obase = dout + (size_t)(b*87 + c*29 + CH0) * HW + outoff;
        #pragma unroll
        for (int d = 0; d < NDIR; d++) {
            float* op = obase + (size_t)d * HW;
            if constexpr (NPX == 4)
                *(float4*)op = make_float4(acc[d][0], acc[d][1], acc[d][2], acc[d][3]);
            else
                *(float2*)op = make_float2(acc[d][0], acc[d][1]);
        }
    }
}

// ---------------- launch ----------------
extern "C" void kernel_launch(void* const* d_in, const int* in_sizes, int n_in,
                              void* d_out, int out_size) {
    const float* x = (const float*)d_in[0];
    float* out = (float*)d_out;

    dim3 grid16(W / 64, H / 16, NIMG);   // 6 x 24 x 24
    dim3 grid32(W / 64, H / 32, NIMG);   // 6 x 12 x 24

    lp_fused_kernel<<<grid16, 256>>>(x, out);

    // scale 0: 4 dirs, 4 px/thread, 512 thr, tile 64x32 one pass
    dir_conv_kernel<0, 0, 4, 4, 0, 4, 32, 512, 1><<<grid32, 512>>>(out);
    // scale 1: 8 dirs, 4 px/thread, 512 thr, tile 64x32 one pass
    dir_conv_kernel<1, 0, 8, 8, 4, 4, 32, 512, 1><<<grid32, 512>>>(out);
    // scale 2: 16 dirs, 2 px/thread, 512 thr, tile 64x32, two passes
    dir_conv_kernel<2, 0, 16, 16, 12, 2, 32, 512, 2><<<grid32, 512>>>(out);
}